// round 11
// baseline (speedup 1.0000x reference)
#include <cuda_runtime.h>
#include <cuda_bf16.h>
#include <cstdint>

#define B 8
#define S 1024
#define DIM 768
#define H 8
#define NEGV -1e10f
#define RS96 0.1020620726159658f  // 1/sqrt(96)
#define NI (B * S)                // 8192 total rows
#define DH 96                     // head dim

// ---------------------------------------------------------------------------
// Scratch (static device globals — allocation-free per harness rules)
// ---------------------------------------------------------------------------
__device__ float g_logit[NI];
__device__ float g_aw[NI];
__device__ float g_R[NI * H];
__device__ float g_T[B * H * DIM];
// bf16 hi/lo splits of inputs
__device__ __nv_bfloat16 g_Xhi[NI * DIM];
__device__ __nv_bfloat16 g_Xlo[NI * DIM];
__device__ __nv_bfloat16 g_Wqhi[DIM * DIM];
__device__ __nv_bfloat16 g_Wqlo[DIM * DIM];
__device__ __nv_bfloat16 g_Wkhi[DIM * DIM];
__device__ __nv_bfloat16 g_Wklo[DIM * DIM];
// head-packed projections: [h][i][d] bf16 hi/lo (RS96 folded into Q)
__device__ __nv_bfloat16 g_Qphi[H * NI * DH];
__device__ __nv_bfloat16 g_Qplo[H * NI * DH];
__device__ __nv_bfloat16 g_Kphi[H * NI * DH];
__device__ __nv_bfloat16 g_Kplo[H * NI * DH];

// ---------------------------------------------------------------------------
#define MMA16816(d, a0, a1, a2, a3, b0, b1)                                    \
    asm volatile("mma.sync.aligned.m16n8k16.row.col.f32.bf16.bf16.f32 "        \
                 "{%0,%1,%2,%3}, {%4,%5,%6,%7}, {%8,%9}, {%0,%1,%2,%3};"       \
                 : "+f"((d)[0]), "+f"((d)[1]), "+f"((d)[2]), "+f"((d)[3])      \
                 : "r"(a0), "r"(a1), "r"(a2), "r"(a3), "r"(b0), "r"(b1))

__device__ __forceinline__ uint32_t packbf2(__nv_bfloat16 a, __nv_bfloat16 b) {
    __nv_bfloat162 p(a, b);
    return *reinterpret_cast<uint32_t*>(&p);
}

// ---------------------------------------------------------------------------
__global__ void k0_zeroR() {
    int i = blockIdx.x * blockDim.x + threadIdx.x;
    if (i < NI * H) g_R[i] = 0.f;
}

// ---------------------------------------------------------------------------
// Ksplit: fp32 -> bf16 hi + bf16 lo. Destinations selected in device code
// (device symbols must never be host-side kernel args).
// ---------------------------------------------------------------------------
__global__ void ksplit_sel(const float* __restrict__ src, int which, int n4) {
    __nv_bfloat16 *hi, *lo;
    if (which == 0)      { hi = g_Xhi;  lo = g_Xlo;  }
    else if (which == 1) { hi = g_Wqhi; lo = g_Wqlo; }
    else                 { hi = g_Wkhi; lo = g_Wklo; }
    int i = blockIdx.x * blockDim.x + threadIdx.x;
    if (i >= n4) return;
    float4 v = ((const float4*)src)[i];
    __nv_bfloat16 h0 = __float2bfloat16(v.x), h1 = __float2bfloat16(v.y);
    __nv_bfloat16 h2 = __float2bfloat16(v.z), h3 = __float2bfloat16(v.w);
    __nv_bfloat16 l0 = __float2bfloat16(v.x - __bfloat162float(h0));
    __nv_bfloat16 l1 = __float2bfloat16(v.y - __bfloat162float(h1));
    __nv_bfloat16 l2 = __float2bfloat16(v.z - __bfloat162float(h2));
    __nv_bfloat16 l3 = __float2bfloat16(v.w - __bfloat162float(h3));
    ((__nv_bfloat162*)hi)[2 * i] = __nv_bfloat162(h0, h1);
    ((__nv_bfloat162*)hi)[2 * i + 1] = __nv_bfloat162(h2, h3);
    ((__nv_bfloat162*)lo)[2 * i] = __nv_bfloat162(l0, l1);
    ((__nv_bfloat162*)lo)[2 * i + 1] = __nv_bfloat162(l2, l3);
}

// ---------------------------------------------------------------------------
// K1a: span logits  l[i] = X[i,:] . w  (masked with NEG where tag==0)
// ---------------------------------------------------------------------------
__global__ void k1a_logits(const float* __restrict__ X,
                           const int* __restrict__ tags,
                           const float* __restrict__ w) {
    int warp = threadIdx.x >> 5, lane = threadIdx.x & 31;
    int row = blockIdx.x * 8 + warp;
    const float4* xr = (const float4*)(X + (size_t)row * DIM);
    const float4* wr = (const float4*)w;
    float s = 0.f;
#pragma unroll
    for (int i = 0; i < 6; i++) {
        float4 a = xr[lane + 32 * i];
        float4 b = wr[lane + 32 * i];
        s += a.x * b.x + a.y * b.y + a.z * b.z + a.w * b.w;
    }
#pragma unroll
    for (int o = 16; o; o >>= 1) s += __shfl_xor_sync(0xffffffffu, s, o);
    if (lane == 0) g_logit[row] = (tags[row] == 0) ? NEGV : s;
}

// ---------------------------------------------------------------------------
__global__ void k1b_softmax() {
    __shared__ float red[256];
    int b = blockIdx.x, t = threadIdx.x;
    float l[4];
#pragma unroll
    for (int i = 0; i < 4; i++) l[i] = g_logit[b * S + t + 256 * i];
    float mx = fmaxf(fmaxf(l[0], l[1]), fmaxf(l[2], l[3]));
    red[t] = mx;
    __syncthreads();
    for (int o = 128; o; o >>= 1) {
        if (t < o) red[t] = fmaxf(red[t], red[t + o]);
        __syncthreads();
    }
    mx = red[0];
    __syncthreads();
    float e[4], sum = 0.f;
#pragma unroll
    for (int i = 0; i < 4; i++) { e[i] = __expf(l[i] - mx); sum += e[i]; }
    red[t] = sum;
    __syncthreads();
    for (int o = 128; o; o >>= 1) {
        if (t < o) red[t] += red[t + o];
        __syncthreads();
    }
    float inv = 1.f / red[0];
#pragma unroll
    for (int i = 0; i < 4; i++) g_aw[b * S + t + 256 * i] = e[i] * inv;
}

// ---------------------------------------------------------------------------
// K2 (mma.sync bf16x3, direct-LDS fragments — VERIFIED mainloop):
// Q = RS96 * X Wq^T, K = X Wk^T, emitted head-packed bf16 hi/lo.
// CTA 128(i) x 64(j), 8 warps (4x2), warp 32x32 dual (Q,K).
// ---------------------------------------------------------------------------
__global__ void __launch_bounds__(256, 2) k2_mma() {
    __shared__ __align__(16) char sbuf[33792];  // max(tiles 20.5KB, Cs 33.8KB)
    __nv_bfloat16* As = (__nv_bfloat16*)sbuf;   // [128][40]
    __nv_bfloat16* Bq = As + 128 * 40;          // [64][40]
    __nv_bfloat16* Bk = Bq + 64 * 40;           // [64][40]
    float* Cs = (float*)sbuf;                   // [128][66] (after mainloop)
    int t = threadIdx.x, l = t & 31, wid = t >> 5;
    int wm = wid & 3, wn = wid >> 2;
    int i0 = blockIdx.x * 128, j0 = blockIdx.y * 64;
    int lg = l >> 2;         // groupID 0..7
    int lk2 = 2 * (l & 3);   // k-pair base 0,2,4,6

    float qacc[2][4][4], kacc[2][4][4];
#pragma unroll
    for (int am = 0; am < 2; am++)
#pragma unroll
        for (int bn = 0; bn < 4; bn++)
#pragma unroll
            for (int r = 0; r < 4; r++) { qacc[am][bn][r] = 0.f; kacc[am][bn][r] = 0.f; }

    for (int term = 0; term < 3; term++) {
        const __nv_bfloat16* XA = (term == 1) ? g_Xlo : g_Xhi;
        const __nv_bfloat16* WQ = (term == 2) ? g_Wqlo : g_Wqhi;
        const __nv_bfloat16* WK = (term == 2) ? g_Wklo : g_Wkhi;
        for (int kb = 0; kb < DIM; kb += 32) {
            int ar = t >> 2, ac = (t & 3) * 8;
            uint4 ra0 = *(const uint4*)(XA + (size_t)(i0 + ar) * DIM + kb + ac);
            uint4 ra1 = *(const uint4*)(XA + (size_t)(i0 + ar + 64) * DIM + kb + ac);
            uint4 rq = *(const uint4*)(WQ + (size_t)(j0 + ar) * DIM + kb + ac);
            uint4 rk = *(const uint4*)(WK + (size_t)(j0 + ar) * DIM + kb + ac);
            __syncthreads();
            *(uint4*)(As + ar * 40 + ac) = ra0;
            *(uint4*)(As + (ar + 64) * 40 + ac) = ra1;
            *(uint4*)(Bq + ar * 40 + ac) = rq;
            *(uint4*)(Bk + ar * 40 + ac) = rk;
            __syncthreads();
#pragma unroll
            for (int kk = 0; kk < 2; kk++) {
                int ko = kk * 16;
                uint32_t a[2][4];
#pragma unroll
                for (int am = 0; am < 2; am++) {
                    const __nv_bfloat16* ap =
                        As + (wm * 32 + am * 16 + lg) * 40 + ko + lk2;
                    a[am][0] = *(const uint32_t*)(ap);
                    a[am][1] = *(const uint32_t*)(ap + 8 * 40);
                    a[am][2] = *(const uint32_t*)(ap + 8);
                    a[am][3] = *(const uint32_t*)(ap + 8 * 40 + 8);
                }
#pragma unroll
                for (int bp = 0; bp < 2; bp++)
#pragma unroll
                    for (int o = 0; o < 2; o++) {
                        int nr = wn * 32 + bp * 16 + o * 8 + lg;
                        const __nv_bfloat16* bqp = Bq + nr * 40 + ko + lk2;
                        uint32_t q0 = *(const uint32_t*)(bqp);
                        uint32_t q1 = *(const uint32_t*)(bqp + 8);
                        MMA16816(qacc[0][2 * bp + o], a[0][0], a[0][1], a[0][2], a[0][3], q0, q1);
                        MMA16816(qacc[1][2 * bp + o], a[1][0], a[1][1], a[1][2], a[1][3], q0, q1);
                        const __nv_bfloat16* bkp = Bk + nr * 40 + ko + lk2;
                        uint32_t k0 = *(const uint32_t*)(bkp);
                        uint32_t k1 = *(const uint32_t*)(bkp + 8);
                        MMA16816(kacc[0][2 * bp + o], a[0][0], a[0][1], a[0][2], a[0][3], k0, k1);
                        MMA16816(kacc[1][2 * bp + o], a[1][0], a[1][1], a[1][2], a[1][3], k0, k1);
                    }
            }
        }
    }

    // Epilogue: stage C in smem [i][j-local], then emit head-packed bf16
    // hi/lo rows: h = j&7, d = j>>3; block covers d0..d0+7 with d0 = j0>>3.
    int d0 = j0 >> 3;
    // ---- Q pass (RS96 folded) ----
    __syncthreads();
#pragma unroll
    for (int am = 0; am < 2; am++)
#pragma unroll
        for (int bn = 0; bn < 4; bn++) {
            int r0 = wm * 32 + am * 16 + lg;
            int c = wn * 32 + bn * 8 + lk2;
            Cs[r0 * 66 + c] = qacc[am][bn][0];
            Cs[r0 * 66 + c + 1] = qacc[am][bn][1];
            Cs[(r0 + 8) * 66 + c] = qacc[am][bn][2];
            Cs[(r0 + 8) * 66 + c + 1] = qacc[am][bn][3];
        }
    __syncthreads();
#pragma unroll
    for (int u = 0; u < 4; u++) {
        int rowid = t + 256 * u;
        int h = rowid & 7, i = rowid >> 3;
        uint4 hv, lv;
        uint32_t* hp = (uint32_t*)&hv;
        uint32_t* lp = (uint32_t*)&lv;
#pragma unroll
        for (int dd = 0; dd < 4; dd++) {
            float v0 = Cs[i * 66 + h + 8 * (2 * dd)] * RS96;
            float v1 = Cs[i * 66 + h + 8 * (2 * dd + 1)] * RS96;
            __nv_bfloat16 h0 = __float2bfloat16(v0), h1 = __float2bfloat16(v1);
            __nv_bfloat16 l0 = __float2bfloat16(v0 - __bfloat162float(h0));
            __nv_bfloat16 l1 = __float2bfloat16(v1 - __bfloat162float(h1));
            hp[dd] = packbf2(h0, h1);
            lp[dd] = packbf2(l0, l1);
        }
        size_t off = ((size_t)h * NI + i0 + i) * DH + d0;
        *(uint4*)(g_Qphi + off) = hv;
        *(uint4*)(g_Qplo + off) = lv;
    }
    // ---- K pass ----
    __syncthreads();
#pragma unroll
    for (int am = 0; am < 2; am++)
#pragma unroll
        for (int bn = 0; bn < 4; bn++) {
            int r0 = wm * 32 + am * 16 + lg;
            int c = wn * 32 + bn * 8 + lk2;
            Cs[r0 * 66 + c] = kacc[am][bn][0];
            Cs[r0 * 66 + c + 1] = kacc[am][bn][1];
            Cs[(r0 + 8) * 66 + c] = kacc[am][bn][2];
            Cs[(r0 + 8) * 66 + c + 1] = kacc[am][bn][3];
        }
    __syncthreads();
#pragma unroll
    for (int u = 0; u < 4; u++) {
        int rowid = t + 256 * u;
        int h = rowid & 7, i = rowid >> 3;
        uint4 hv, lv;
        uint32_t* hp = (uint32_t*)&hv;
        uint32_t* lp = (uint32_t*)&lv;
#pragma unroll
        for (int dd = 0; dd < 4; dd++) {
            float v0 = Cs[i * 66 + h + 8 * (2 * dd)];
            float v1 = Cs[i * 66 + h + 8 * (2 * dd + 1)];
            __nv_bfloat16 h0 = __float2bfloat16(v0), h1 = __float2bfloat16(v1);
            __nv_bfloat16 l0 = __float2bfloat16(v0 - __bfloat162float(h0));
            __nv_bfloat16 l1 = __float2bfloat16(v1 - __bfloat162float(h1));
            hp[dd] = packbf2(h0, h1);
            lp[dd] = packbf2(l0, l1);
        }
        size_t off = ((size_t)h * NI + i0 + i) * DH + d0;
        *(uint4*)(g_Kphi + off) = hv;
        *(uint4*)(g_Kplo + off) = lv;
    }
}

// ---------------------------------------------------------------------------
// K3 (mma.sync bf16x3, direct-LDS fragments): per-head logits GEMM over
// d=96; all 8 heads of a (q,k) pair in one thread -> in-register heads
// softmax; aw-weighted q-reduction via shuffles + atomics into R[b,k,h].
// CTA: q64 x k32, 8 warps (4q x 2k), warp q16 x k16.
// ---------------------------------------------------------------------------
__global__ void __launch_bounds__(256, 2) k3_attn() {
    __shared__ __align__(16) __nv_bfloat16 Qs[8 * 64 * 24];  // [h][q][16+8pad]
    __shared__ __align__(16) __nv_bfloat16 Ks[8 * 32 * 24];  // [h][k][16+8pad]
    __shared__ float Rs[32][8];
    int b = blockIdx.z, q0 = blockIdx.y * 64, k0 = blockIdx.x * 32;
    int t = threadIdx.x, l = t & 31, wid = t >> 5;
    int wq = wid & 3, wk = wid >> 2;
    int lg = l >> 2, lk2 = 2 * (l & 3);
    int iq = b * S + q0, ik = b * S + k0;
    ((float*)Rs)[t] = 0.f;

    float acc[8][2][4];  // [head][n8-block][reg]
#pragma unroll
    for (int h = 0; h < 8; h++)
#pragma unroll
        for (int bn = 0; bn < 2; bn++)
#pragma unroll
            for (int r = 0; r < 4; r++) acc[h][bn][r] = 0.f;

    for (int term = 0; term < 3; term++) {
        const __nv_bfloat16* Qsrc = (term == 1) ? g_Qplo : g_Qphi;
        const __nv_bfloat16* Ksrc = (term == 2) ? g_Kplo : g_Kphi;
        for (int dd0 = 0; dd0 < DH; dd0 += 16) {
            // Q rows: 512 = [h][q]; thread t loads rows t and t+256 (32B each)
            int h0 = t >> 6, qq = t & 63;
            const uint4* pq0 = (const uint4*)(Qsrc + ((size_t)h0 * NI + iq + qq) * DH + dd0);
            uint4 qa = pq0[0], qb = pq0[1];
            int h1 = (t + 256) >> 6;
            const uint4* pq1 = (const uint4*)(Qsrc + ((size_t)h1 * NI + iq + qq) * DH + dd0);
            uint4 qc = pq1[0], qd = pq1[1];
            // K rows: 256 = [h][k]
            int hk = t >> 5, kk2 = t & 31;
            const uint4* pk = (const uint4*)(Ksrc + ((size_t)hk * NI + ik + kk2) * DH + dd0);
            uint4 ka = pk[0], kb2 = pk[1];
            __syncthreads();
            *(uint4*)(Qs + t * 24) = qa;
            *(uint4*)(Qs + t * 24 + 8) = qb;
            *(uint4*)(Qs + (t + 256) * 24) = qc;
            *(uint4*)(Qs + (t + 256) * 24 + 8) = qd;
            *(uint4*)(Ks + t * 24) = ka;
            *(uint4*)(Ks + t * 24 + 8) = kb2;
            __syncthreads();
#pragma unroll
            for (int h = 0; h < 8; h++) {
                // A fragment (q16 x d16), direct LDS (verified pattern)
                const __nv_bfloat16* ap = Qs + (h * 64 + wq * 16 + lg) * 24 + lk2;
                uint32_t a0 = *(const uint32_t*)(ap);
                uint32_t a1 = *(const uint32_t*)(ap + 8 * 24);
                uint32_t a2 = *(const uint32_t*)(ap + 8);
                uint32_t a3 = *(const uint32_t*)(ap + 8 * 24 + 8);
#pragma unroll
                for (int o = 0; o < 2; o++) {
                    const __nv_bfloat16* bp = Ks + (h * 32 + wk * 16 + o * 8 + lg) * 24 + lk2;
                    uint32_t b0 = *(const uint32_t*)(bp);
                    uint32_t b1 = *(const uint32_t*)(bp + 8);
                    MMA16816(acc[h][o], a0, a1, a2, a3, b0, b1);
                }
            }
        }
    }

    // Epilogue: c-frag (g,2c)/(g,2c+1)/(g+8,2c)/(g+8,2c+1); softmax over h.
    float aw0 = g_aw[iq + wq * 16 + lg];
    float aw1 = g_aw[iq + wq * 16 + lg + 8];
#pragma unroll
    for (int bn = 0; bn < 2; bn++) {
        float rk[2][8];
#pragma unroll
        for (int ci = 0; ci < 2; ci++)
#pragma unroll
            for (int h = 0; h < 8; h++) rk[ci][h] = 0.f;
#pragma unroll
        for (int ci = 0; ci < 2; ci++)
#pragma unroll
            for (int ri = 0; ri < 2; ri++) {
                float aw = ri ? aw1 : aw0;
                float v[8];
#pragma unroll
                for (int h = 0; h < 8; h++) v[h] = acc[h][bn][ri * 2 + ci];
                float m = v[0];
#pragma unroll
                for (int h = 1; h < 8; h++) m = fmaxf(m, v[h]);
                float e[8], s = 0.f;
#pragma unroll
                for (int h = 0; h < 8; h++) { e[h] = __expf(v[h] - m); s += e[h]; }
                float w = __fdividef(aw, s);
#pragma unroll
                for (int h = 0; h < 8; h++) rk[ci][h] += w * e[h];
            }
        // reduce over the warp's 16 q-rows (lanes differing in bits 2..4)
#pragma unroll
        for (int ci = 0; ci < 2; ci++)
#pragma unroll
            for (int h = 0; h < 8; h++) {
                float r = rk[ci][h];
                r += __shfl_xor_sync(0xffffffffu, r, 4);
                r += __shfl_xor_sync(0xffffffffu, r, 8);
                r += __shfl_xor_sync(0xffffffffu, r, 16);
                if (l < 4) {
                    int kl = wk * 16 + bn * 8 + 2 * l + ci;
                    atomicAdd(&Rs[kl][h], r);
                }
            }
    }
    __syncthreads();
    atomicAdd(&g_R[(size_t)(ik + (t >> 3)) * H + (t & 7)], Rs[t >> 3][t & 7]);
}

// ---------------------------------------------------------------------------
// K4: T[b,h,m] = sum_k R[b,k,h] * X[b,k,m]
// ---------------------------------------------------------------------------
__global__ void __launch_bounds__(256) k4_T(const float* __restrict__ X) {
    __shared__ float Xs[64][64];
    __shared__ float Rsm[64][8];
    int b = blockIdx.y;
    int m0 = blockIdx.x * 64;
    int t = threadIdx.x;
    int m = t & 63, hh = t >> 6;
    float acc0 = 0.f, acc1 = 0.f;
    for (int kc = 0; kc < S; kc += 64) {
#pragma unroll
        for (int u = 0; u < 4; u++) {
            int lin = t + 256 * u;
            int r = lin >> 4, c = (lin & 15) << 2;
            *(float4*)&Xs[r][c] =
                *(const float4*)(X + (size_t)(b * S + kc + r) * DIM + m0 + c);
        }
        {
            float2 v = *(const float2*)(g_R + ((size_t)b * S + kc) * H + t * 2);
            *(float2*)&((float*)Rsm)[t * 2] = v;
        }
        __syncthreads();
#pragma unroll 8
        for (int k = 0; k < 64; k++) {
            float x = Xs[k][m];
            acc0 += Rsm[k][hh] * x;
            acc1 += Rsm[k][hh + 4] * x;
        }
        __syncthreads();
    }
    g_T[((size_t)b * H + hh) * DIM + m0 + m] = acc0;
    g_T[((size_t)b * H + hh + 4) * DIM + m0 + m] = acc1;
}

// ---------------------------------------------------------------------------
// K5: out[b,j] = sum_m Wv[j,m] * T[b, j&7, m]
// ---------------------------------------------------------------------------
__global__ void k5_out(const float* __restrict__ Wv, float* __restrict__ out) {
    int warp = threadIdx.x >> 5, lane = threadIdx.x & 31;
    int g = blockIdx.x * 8 + warp;
    int b = g / DIM, j = g % DIM;
    int h = j & 7;
    const float4* wr = (const float4*)(Wv + (size_t)j * DIM);
    const float4* tr = (const float4*)(g_T + ((size_t)b * H + h) * DIM);
    float s = 0.f;
#pragma unroll
    for (int i = 0; i < 6; i++) {
        float4 a = wr[lane + 32 * i];
        float4 c = tr[lane + 32 * i];
        s += a.x * c.x + a.y * c.y + a.z * c.z + a.w * c.w;
    }
#pragma unroll
    for (int o = 16; o; o >>= 1) s += __shfl_xor_sync(0xffffffffu, s, o);
    if (lane == 0) out[(size_t)b * DIM + j] = s;
}

// ---------------------------------------------------------------------------
extern "C" void kernel_launch(void* const* d_in, const int* in_sizes, int n_in,
                              void* d_out, int out_size) {
    const float* X    = (const float*)d_in[0];
    const int*   tags = (const int*)d_in[1];
    const float* w    = (const float*)d_in[2];
    const float* Wq   = (const float*)d_in[3];
    const float* Wk   = (const float*)d_in[4];
    const float* Wv   = (const float*)d_in[5];
    float* out = (float*)d_out;

    k0_zeroR<<<(NI * H + 255) / 256, 256>>>();
    ksplit_sel<<<(NI * DIM / 4 + 255) / 256, 256>>>(X, 0, NI * DIM / 4);
    ksplit_sel<<<(DIM * DIM / 4 + 255) / 256, 256>>>(Wq, 1, DIM * DIM / 4);
    ksplit_sel<<<(DIM * DIM / 4 + 255) / 256, 256>>>(Wk, 2, DIM * DIM / 4);
    k1a_logits<<<NI / 8, 256>>>(X, tags, w);
    k1b_softmax<<<B, 256>>>();
    k2_mma<<<dim3(64, 12), 256>>>();
    k3_attn<<<dim3(32, 16, 8), 256>>>();
    k4_T<<<dim3(12, 8), 256>>>(X);
    k5_out<<<768, 256>>>(Wv, out);
}

// round 14
// speedup vs baseline: 1.3375x; 1.3375x over previous
#include <cuda_runtime.h>
#include <cuda_bf16.h>
#include <cstdint>

#define B 8
#define S 1024
#define DIM 768
#define H 8
#define NEGV -1e10f
#define RS96 0.1020620726159658f  // 1/sqrt(96)
#define NI (B * S)                // 8192 total rows
#define DH 96                     // head dim

// ---------------------------------------------------------------------------
// Scratch (static device globals — allocation-free per harness rules)
// ---------------------------------------------------------------------------
__device__ float g_logit[NI];
__device__ float g_aw[NI];
__device__ float g_R[NI * H];
__device__ float g_T[B * H * DIM];
// bf16 hi/lo splits of inputs
__device__ __nv_bfloat16 g_Xhi[NI * DIM];
__device__ __nv_bfloat16 g_Xlo[NI * DIM];
__device__ __nv_bfloat16 g_Wqhi[DIM * DIM];
__device__ __nv_bfloat16 g_Wqlo[DIM * DIM];
__device__ __nv_bfloat16 g_Wkhi[DIM * DIM];
__device__ __nv_bfloat16 g_Wklo[DIM * DIM];
// head-packed projections: [h][i][d] bf16 hi/lo (RS96 folded into Q)
__device__ __nv_bfloat16 g_Qphi[H * NI * DH];
__device__ __nv_bfloat16 g_Qplo[H * NI * DH];
__device__ __nv_bfloat16 g_Kphi[H * NI * DH];
__device__ __nv_bfloat16 g_Kplo[H * NI * DH];

// ---------------------------------------------------------------------------
#define MMA16816(d, a0, a1, a2, a3, b0, b1)                                    \
    asm volatile("mma.sync.aligned.m16n8k16.row.col.f32.bf16.bf16.f32 "        \
                 "{%0,%1,%2,%3}, {%4,%5,%6,%7}, {%8,%9}, {%0,%1,%2,%3};"       \
                 : "+f"((d)[0]), "+f"((d)[1]), "+f"((d)[2]), "+f"((d)[3])      \
                 : "r"(a0), "r"(a1), "r"(a2), "r"(a3), "r"(b0), "r"(b1))

__device__ __forceinline__ uint32_t packbf2(__nv_bfloat16 a, __nv_bfloat16 b) {
    __nv_bfloat162 p(a, b);
    return *reinterpret_cast<uint32_t*>(&p);
}

// ---------------------------------------------------------------------------
__global__ void k0_zeroR() {
    int i = blockIdx.x * blockDim.x + threadIdx.x;
    if (i < NI * H) g_R[i] = 0.f;
}

// ---------------------------------------------------------------------------
// Ksplit: fp32 -> bf16 hi + bf16 lo. Destinations selected in device code
// (device symbols must never be host-side kernel args).
// ---------------------------------------------------------------------------
__global__ void ksplit_sel(const float* __restrict__ src, int which, int n4) {
    __nv_bfloat16 *hi, *lo;
    if (which == 0)      { hi = g_Xhi;  lo = g_Xlo;  }
    else if (which == 1) { hi = g_Wqhi; lo = g_Wqlo; }
    else                 { hi = g_Wkhi; lo = g_Wklo; }
    int i = blockIdx.x * blockDim.x + threadIdx.x;
    if (i >= n4) return;
    float4 v = ((const float4*)src)[i];
    __nv_bfloat16 h0 = __float2bfloat16(v.x), h1 = __float2bfloat16(v.y);
    __nv_bfloat16 h2 = __float2bfloat16(v.z), h3 = __float2bfloat16(v.w);
    __nv_bfloat16 l0 = __float2bfloat16(v.x - __bfloat162float(h0));
    __nv_bfloat16 l1 = __float2bfloat16(v.y - __bfloat162float(h1));
    __nv_bfloat16 l2 = __float2bfloat16(v.z - __bfloat162float(h2));
    __nv_bfloat16 l3 = __float2bfloat16(v.w - __bfloat162float(h3));
    ((__nv_bfloat162*)hi)[2 * i] = __nv_bfloat162(h0, h1);
    ((__nv_bfloat162*)hi)[2 * i + 1] = __nv_bfloat162(h2, h3);
    ((__nv_bfloat162*)lo)[2 * i] = __nv_bfloat162(l0, l1);
    ((__nv_bfloat162*)lo)[2 * i + 1] = __nv_bfloat162(l2, l3);
}

// ---------------------------------------------------------------------------
// K1a: span logits  l[i] = X[i,:] . w  (masked with NEG where tag==0)
// ---------------------------------------------------------------------------
__global__ void k1a_logits(const float* __restrict__ X,
                           const int* __restrict__ tags,
                           const float* __restrict__ w) {
    int warp = threadIdx.x >> 5, lane = threadIdx.x & 31;
    int row = blockIdx.x * 8 + warp;
    const float4* xr = (const float4*)(X + (size_t)row * DIM);
    const float4* wr = (const float4*)w;
    float s = 0.f;
#pragma unroll
    for (int i = 0; i < 6; i++) {
        float4 a = xr[lane + 32 * i];
        float4 b = wr[lane + 32 * i];
        s += a.x * b.x + a.y * b.y + a.z * b.z + a.w * b.w;
    }
#pragma unroll
    for (int o = 16; o; o >>= 1) s += __shfl_xor_sync(0xffffffffu, s, o);
    if (lane == 0) g_logit[row] = (tags[row] == 0) ? NEGV : s;
}

// ---------------------------------------------------------------------------
__global__ void k1b_softmax() {
    __shared__ float red[256];
    int b = blockIdx.x, t = threadIdx.x;
    float l[4];
#pragma unroll
    for (int i = 0; i < 4; i++) l[i] = g_logit[b * S + t + 256 * i];
    float mx = fmaxf(fmaxf(l[0], l[1]), fmaxf(l[2], l[3]));
    red[t] = mx;
    __syncthreads();
    for (int o = 128; o; o >>= 1) {
        if (t < o) red[t] = fmaxf(red[t], red[t + o]);
        __syncthreads();
    }
    mx = red[0];
    __syncthreads();
    float e[4], sum = 0.f;
#pragma unroll
    for (int i = 0; i < 4; i++) { e[i] = __expf(l[i] - mx); sum += e[i]; }
    red[t] = sum;
    __syncthreads();
    for (int o = 128; o; o >>= 1) {
        if (t < o) red[t] += red[t + o];
        __syncthreads();
    }
    float inv = 1.f / red[0];
#pragma unroll
    for (int i = 0; i < 4; i++) g_aw[b * S + t + 256 * i] = e[i] * inv;
}

// ---------------------------------------------------------------------------
// K2 (mma.sync bf16x3, direct-LDS fragments — VERIFIED):
// Q = RS96 * X Wq^T, K = X Wk^T, emitted head-packed bf16 hi/lo.
// CTA 128(i) x 64(j), 8 warps (4x2), warp 32x32 dual (Q,K).
// ---------------------------------------------------------------------------
__global__ void __launch_bounds__(256, 2) k2_mma() {
    __shared__ __align__(16) char sbuf[33792];
    __nv_bfloat16* As = (__nv_bfloat16*)sbuf;   // [128][40]
    __nv_bfloat16* Bq = As + 128 * 40;          // [64][40]
    __nv_bfloat16* Bk = Bq + 64 * 40;           // [64][40]
    float* Cs = (float*)sbuf;                   // [128][66] (after mainloop)
    int t = threadIdx.x, l = t & 31, wid = t >> 5;
    int wm = wid & 3, wn = wid >> 2;
    int i0 = blockIdx.x * 128, j0 = blockIdx.y * 64;
    int lg = l >> 2;         // groupID 0..7
    int lk2 = 2 * (l & 3);   // k-pair base 0,2,4,6

    float qacc[2][4][4], kacc[2][4][4];
#pragma unroll
    for (int am = 0; am < 2; am++)
#pragma unroll
        for (int bn = 0; bn < 4; bn++)
#pragma unroll
            for (int r = 0; r < 4; r++) { qacc[am][bn][r] = 0.f; kacc[am][bn][r] = 0.f; }

    for (int term = 0; term < 3; term++) {
        const __nv_bfloat16* XA = (term == 1) ? g_Xlo : g_Xhi;
        const __nv_bfloat16* WQ = (term == 2) ? g_Wqlo : g_Wqhi;
        const __nv_bfloat16* WK = (term == 2) ? g_Wklo : g_Wkhi;
        for (int kb = 0; kb < DIM; kb += 32) {
            int ar = t >> 2, ac = (t & 3) * 8;
            uint4 ra0 = *(const uint4*)(XA + (size_t)(i0 + ar) * DIM + kb + ac);
            uint4 ra1 = *(const uint4*)(XA + (size_t)(i0 + ar + 64) * DIM + kb + ac);
            uint4 rq = *(const uint4*)(WQ + (size_t)(j0 + ar) * DIM + kb + ac);
            uint4 rk = *(const uint4*)(WK + (size_t)(j0 + ar) * DIM + kb + ac);
            __syncthreads();
            *(uint4*)(As + ar * 40 + ac) = ra0;
            *(uint4*)(As + (ar + 64) * 40 + ac) = ra1;
            *(uint4*)(Bq + ar * 40 + ac) = rq;
            *(uint4*)(Bk + ar * 40 + ac) = rk;
            __syncthreads();
#pragma unroll
            for (int kk = 0; kk < 2; kk++) {
                int ko = kk * 16;
                uint32_t a[2][4];
#pragma unroll
                for (int am = 0; am < 2; am++) {
                    const __nv_bfloat16* ap =
                        As + (wm * 32 + am * 16 + lg) * 40 + ko + lk2;
                    a[am][0] = *(const uint32_t*)(ap);
                    a[am][1] = *(const uint32_t*)(ap + 8 * 40);
                    a[am][2] = *(const uint32_t*)(ap + 8);
                    a[am][3] = *(const uint32_t*)(ap + 8 * 40 + 8);
                }
#pragma unroll
                for (int bp = 0; bp < 2; bp++)
#pragma unroll
                    for (int o = 0; o < 2; o++) {
                        int nr = wn * 32 + bp * 16 + o * 8 + lg;
                        const __nv_bfloat16* bqp = Bq + nr * 40 + ko + lk2;
                        uint32_t q0 = *(const uint32_t*)(bqp);
                        uint32_t q1 = *(const uint32_t*)(bqp + 8);
                        MMA16816(qacc[0][2 * bp + o], a[0][0], a[0][1], a[0][2], a[0][3], q0, q1);
                        MMA16816(qacc[1][2 * bp + o], a[1][0], a[1][1], a[1][2], a[1][3], q0, q1);
                        const __nv_bfloat16* bkp = Bk + nr * 40 + ko + lk2;
                        uint32_t k0 = *(const uint32_t*)(bkp);
                        uint32_t k1 = *(const uint32_t*)(bkp + 8);
                        MMA16816(kacc[0][2 * bp + o], a[0][0], a[0][1], a[0][2], a[0][3], k0, k1);
                        MMA16816(kacc[1][2 * bp + o], a[1][0], a[1][1], a[1][2], a[1][3], k0, k1);
                    }
            }
        }
    }

    int d0 = j0 >> 3;
    // ---- Q pass (RS96 folded) ----
    __syncthreads();
#pragma unroll
    for (int am = 0; am < 2; am++)
#pragma unroll
        for (int bn = 0; bn < 4; bn++) {
            int r0 = wm * 32 + am * 16 + lg;
            int c = wn * 32 + bn * 8 + lk2;
            Cs[r0 * 66 + c] = qacc[am][bn][0];
            Cs[r0 * 66 + c + 1] = qacc[am][bn][1];
            Cs[(r0 + 8) * 66 + c] = qacc[am][bn][2];
            Cs[(r0 + 8) * 66 + c + 1] = qacc[am][bn][3];
        }
    __syncthreads();
#pragma unroll
    for (int u = 0; u < 4; u++) {
        int rowid = t + 256 * u;
        int h = rowid & 7, i = rowid >> 3;
        uint4 hv, lv;
        uint32_t* hp = (uint32_t*)&hv;
        uint32_t* lp = (uint32_t*)&lv;
#pragma unroll
        for (int dd = 0; dd < 4; dd++) {
            float v0 = Cs[i * 66 + h + 8 * (2 * dd)] * RS96;
            float v1 = Cs[i * 66 + h + 8 * (2 * dd + 1)] * RS96;
            __nv_bfloat16 h0 = __float2bfloat16(v0), h1 = __float2bfloat16(v1);
            __nv_bfloat16 l0 = __float2bfloat16(v0 - __bfloat162float(h0));
            __nv_bfloat16 l1 = __float2bfloat16(v1 - __bfloat162float(h1));
            hp[dd] = packbf2(h0, h1);
            lp[dd] = packbf2(l0, l1);
        }
        size_t off = ((size_t)h * NI + i0 + i) * DH + d0;
        *(uint4*)(g_Qphi + off) = hv;
        *(uint4*)(g_Qplo + off) = lv;
    }
    // ---- K pass ----
    __syncthreads();
#pragma unroll
    for (int am = 0; am < 2; am++)
#pragma unroll
        for (int bn = 0; bn < 4; bn++) {
            int r0 = wm * 32 + am * 16 + lg;
            int c = wn * 32 + bn * 8 + lk2;
            Cs[r0 * 66 + c] = kacc[am][bn][0];
            Cs[r0 * 66 + c + 1] = kacc[am][bn][1];
            Cs[(r0 + 8) * 66 + c] = kacc[am][bn][2];
            Cs[(r0 + 8) * 66 + c + 1] = kacc[am][bn][3];
        }
    __syncthreads();
#pragma unroll
    for (int u = 0; u < 4; u++) {
        int rowid = t + 256 * u;
        int h = rowid & 7, i = rowid >> 3;
        uint4 hv, lv;
        uint32_t* hp = (uint32_t*)&hv;
        uint32_t* lp = (uint32_t*)&lv;
#pragma unroll
        for (int dd = 0; dd < 4; dd++) {
            float v0 = Cs[i * 66 + h + 8 * (2 * dd)];
            float v1 = Cs[i * 66 + h + 8 * (2 * dd + 1)];
            __nv_bfloat16 h0 = __float2bfloat16(v0), h1 = __float2bfloat16(v1);
            __nv_bfloat16 l0 = __float2bfloat16(v0 - __bfloat162float(h0));
            __nv_bfloat16 l1 = __float2bfloat16(v1 - __bfloat162float(h1));
            hp[dd] = packbf2(h0, h1);
            lp[dd] = packbf2(l0, l1);
        }
        size_t off = ((size_t)h * NI + i0 + i) * DH + d0;
        *(uint4*)(g_Kphi + off) = hv;
        *(uint4*)(g_Kplo + off) = lv;
    }
}

// ---------------------------------------------------------------------------
// K3 (mma.sync bf16x3): q64 x k64 tiles, 512 threads, 16 warps (4q x 4k).
// Per d16 chunk, ALL FOUR tiles (Qhi,Qlo,Khi,Klo) staged once (TWO uint4 =
// 16 bf16 per row — R13's NaN was loading only 8); 3 term MMAs per fragment.
// Dynamic smem: 4 tiles x [8][64][24] bf16 = 96 KB.
// ---------------------------------------------------------------------------
#define K3_TILE (8 * 64 * 24)
__global__ void __launch_bounds__(512, 1) k3_attn() {
    extern __shared__ __align__(16) __nv_bfloat16 sm3[];
    __nv_bfloat16* Qh = sm3;
    __nv_bfloat16* Ql = Qh + K3_TILE;
    __nv_bfloat16* Kh = Ql + K3_TILE;
    __nv_bfloat16* Kl = Kh + K3_TILE;
    __shared__ float Rs[64][8];
    int b = blockIdx.z, q0 = blockIdx.y * 64, k0 = blockIdx.x * 64;
    int t = threadIdx.x, l = t & 31, wid = t >> 5;
    int wq = wid & 3, wk = wid >> 2;  // 4q x 4k
    int lg = l >> 2, lk2 = 2 * (l & 3);
    int iq = b * S + q0, ik = b * S + k0;
    ((float*)Rs)[t] = 0.f;

    float acc[8][2][4];  // [head][n8-block][reg]
#pragma unroll
    for (int h = 0; h < 8; h++)
#pragma unroll
        for (int bn = 0; bn < 2; bn++)
#pragma unroll
            for (int r = 0; r < 4; r++) acc[h][bn][r] = 0.f;

    // loader: 512 rows per tile ([h][row]); thread t owns row t; each d16
    // chunk is 16 bf16 = TWO uint4 per tile.
    int lh = t >> 6, lrow = t & 63;
    size_t qoff = ((size_t)lh * NI + iq + lrow) * DH;
    size_t koff = ((size_t)lh * NI + ik + lrow) * DH;

    for (int dd0 = 0; dd0 < DH; dd0 += 16) {
        const uint4* pqh = (const uint4*)(g_Qphi + qoff + dd0);
        const uint4* pql = (const uint4*)(g_Qplo + qoff + dd0);
        const uint4* pkh = (const uint4*)(g_Kphi + koff + dd0);
        const uint4* pkl = (const uint4*)(g_Kplo + koff + dd0);
        uint4 vqh0 = pqh[0], vqh1 = pqh[1];
        uint4 vql0 = pql[0], vql1 = pql[1];
        uint4 vkh0 = pkh[0], vkh1 = pkh[1];
        uint4 vkl0 = pkl[0], vkl1 = pkl[1];
        __syncthreads();
        *(uint4*)(Qh + t * 24) = vqh0;  *(uint4*)(Qh + t * 24 + 8) = vqh1;
        *(uint4*)(Ql + t * 24) = vql0;  *(uint4*)(Ql + t * 24 + 8) = vql1;
        *(uint4*)(Kh + t * 24) = vkh0;  *(uint4*)(Kh + t * 24 + 8) = vkh1;
        *(uint4*)(Kl + t * 24) = vkl0;  *(uint4*)(Kl + t * 24 + 8) = vkl1;
        __syncthreads();
#pragma unroll
        for (int h = 0; h < 8; h++) {
            int arow = (h * 64 + wq * 16 + lg) * 24 + lk2;
            const __nv_bfloat16* aph = Qh + arow;
            uint32_t ah0 = *(const uint32_t*)(aph);
            uint32_t ah1 = *(const uint32_t*)(aph + 8 * 24);
            uint32_t ah2 = *(const uint32_t*)(aph + 8);
            uint32_t ah3 = *(const uint32_t*)(aph + 8 * 24 + 8);
            const __nv_bfloat16* apl = Ql + arow;
            uint32_t al0 = *(const uint32_t*)(apl);
            uint32_t al1 = *(const uint32_t*)(apl + 8 * 24);
            uint32_t al2 = *(const uint32_t*)(apl + 8);
            uint32_t al3 = *(const uint32_t*)(apl + 8 * 24 + 8);
#pragma unroll
            for (int o = 0; o < 2; o++) {
                int brow = (h * 64 + wk * 16 + o * 8 + lg) * 24 + lk2;
                const __nv_bfloat16* bph = Kh + brow;
                uint32_t bh0 = *(const uint32_t*)(bph);
                uint32_t bh1 = *(const uint32_t*)(bph + 8);
                const __nv_bfloat16* bpl = Kl + brow;
                uint32_t bl0 = *(const uint32_t*)(bpl);
                uint32_t bl1 = *(const uint32_t*)(bpl + 8);
                MMA16816(acc[h][o], ah0, ah1, ah2, ah3, bh0, bh1);  // hi.hi
                MMA16816(acc[h][o], al0, al1, al2, al3, bh0, bh1);  // lo.hi
                MMA16816(acc[h][o], ah0, ah1, ah2, ah3, bl0, bl1);  // hi.lo
            }
        }
    }

    // Epilogue (verified mapping): c-frag rows g (ri=0) and g+8 (ri=1),
    // cols 2c (ci=0), 2c+1 (ci=1); softmax over h, aw-weighted q-reduction.
    float aw0 = g_aw[iq + wq * 16 + lg];
    float aw1 = g_aw[iq + wq * 16 + lg + 8];
#pragma unroll
    for (int bn = 0; bn < 2; bn++) {
        float rk[2][8];
#pragma unroll
        for (int ci = 0; ci < 2; ci++)
#pragma unroll
            for (int h = 0; h < 8; h++) rk[ci][h] = 0.f;
#pragma unroll
        for (int ci = 0; ci < 2; ci++)
#pragma unroll
            for (int ri = 0; ri < 2; ri++) {
                float aw = ri ? aw1 : aw0;
                float v[8];
#pragma unroll
                for (int h = 0; h < 8; h++) v[h] = acc[h][bn][ri * 2 + ci];
                float m = v[0];
#pragma unroll
                for (int h = 1; h < 8; h++) m = fmaxf(m, v[h]);
                float e[8], s = 0.f;
#pragma unroll
                for (int h = 0; h < 8; h++) { e[h] = __expf(v[h] - m); s += e[h]; }
                float w = __fdividef(aw, s);
#pragma unroll
                for (int h = 0; h < 8; h++) rk[ci][h] += w * e[h];
            }
#pragma unroll
        for (int ci = 0; ci < 2; ci++)
#pragma unroll
            for (int h = 0; h < 8; h++) {
                float r = rk[ci][h];
                r += __shfl_xor_sync(0xffffffffu, r, 4);
                r += __shfl_xor_sync(0xffffffffu, r, 8);
                r += __shfl_xor_sync(0xffffffffu, r, 16);
                if (l < 4) {
                    int kl = wk * 16 + bn * 8 + 2 * l + ci;
                    atomicAdd(&Rs[kl][h], r);
                }
            }
    }
    __syncthreads();
    atomicAdd(&g_R[(size_t)(ik + (t >> 3)) * H + (t & 7)], Rs[t >> 3][t & 7]);
}

// ---------------------------------------------------------------------------
// K4: T[b,h,m] = sum_k R[b,k,h] * X[b,k,m]
// ---------------------------------------------------------------------------
__global__ void __launch_bounds__(256) k4_T(const float* __restrict__ X) {
    __shared__ float Xs[64][64];
    __shared__ float Rsm[64][8];
    int b = blockIdx.y;
    int m0 = blockIdx.x * 64;
    int t = threadIdx.x;
    int m = t & 63, hh = t >> 6;
    float acc0 = 0.f, acc1 = 0.f;
    for (int kc = 0; kc < S; kc += 64) {
#pragma unroll
        for (int u = 0; u < 4; u++) {
            int lin = t + 256 * u;
            int r = lin >> 4, c = (lin & 15) << 2;
            *(float4*)&Xs[r][c] =
                *(const float4*)(X + (size_t)(b * S + kc + r) * DIM + m0 + c);
        }
        {
            float2 v = *(const float2*)(g_R + ((size_t)b * S + kc) * H + t * 2);
            *(float2*)&((float*)Rsm)[t * 2] = v;
        }
        __syncthreads();
#pragma unroll 8
        for (int k = 0; k < 64; k++) {
            float x = Xs[k][m];
            acc0 += Rsm[k][hh] * x;
            acc1 += Rsm[k][hh + 4] * x;
        }
        __syncthreads();
    }
    g_T[((size_t)b * H + hh) * DIM + m0 + m] = acc0;
    g_T[((size_t)b * H + hh + 4) * DIM + m0 + m] = acc1;
}

// ---------------------------------------------------------------------------
// K5: out[b,j] = sum_m Wv[j,m] * T[b, j&7, m]
// ---------------------------------------------------------------------------
__global__ void k5_out(const float* __restrict__ Wv, float* __restrict__ out) {
    int warp = threadIdx.x >> 5, lane = threadIdx.x & 31;
    int g = blockIdx.x * 8 + warp;
    int b = g / DIM, j = g % DIM;
    int h = j & 7;
    const float4* wr = (const float4*)(Wv + (size_t)j * DIM);
    const float4* tr = (const float4*)(g_T + ((size_t)b * H + h) * DIM);
    float s = 0.f;
#pragma unroll
    for (int i = 0; i < 6; i++) {
        float4 a = wr[lane + 32 * i];
        float4 c = tr[lane + 32 * i];
        s += a.x * c.x + a.y * c.y + a.z * c.z + a.w * c.w;
    }
#pragma unroll
    for (int o = 16; o; o >>= 1) s += __shfl_xor_sync(0xffffffffu, s, o);
    if (lane == 0) out[(size_t)b * DIM + j] = s;
}

// ---------------------------------------------------------------------------
extern "C" void kernel_launch(void* const* d_in, const int* in_sizes, int n_in,
                              void* d_out, int out_size) {
    const float* X    = (const float*)d_in[0];
    const int*   tags = (const int*)d_in[1];
    const float* w    = (const float*)d_in[2];
    const float* Wq   = (const float*)d_in[3];
    const float* Wk   = (const float*)d_in[4];
    const float* Wv   = (const float*)d_in[5];
    float* out = (float*)d_out;

    static int k3_smem_set = 0;
    if (!k3_smem_set) {
        cudaFuncSetAttribute(k3_attn, cudaFuncAttributeMaxDynamicSharedMemorySize,
                             4 * K3_TILE * (int)sizeof(__nv_bfloat16));
        k3_smem_set = 1;
    }

    k0_zeroR<<<(NI * H + 255) / 256, 256>>>();
    ksplit_sel<<<(NI * DIM / 4 + 255) / 256, 256>>>(X, 0, NI * DIM / 4);
    ksplit_sel<<<(DIM * DIM / 4 + 255) / 256, 256>>>(Wq, 1, DIM * DIM / 4);
    ksplit_sel<<<(DIM * DIM / 4 + 255) / 256, 256>>>(Wk, 2, DIM * DIM / 4);
    k1a_logits<<<NI / 8, 256>>>(X, tags, w);
    k1b_softmax<<<B, 256>>>();
    k2_mma<<<dim3(64, 12), 256>>>();
    k3_attn<<<dim3(16, 16, 8), 512, 4 * K3_TILE * sizeof(__nv_bfloat16)>>>();
    k4_T<<<dim3(12, 8), 256>>>(X);
    k5_out<<<768, 256>>>(Wv, out);
}

// round 15
// speedup vs baseline: 1.3735x; 1.0269x over previous
#include <cuda_runtime.h>
#include <cuda_bf16.h>
#include <cstdint>

#define B 8
#define S 1024
#define DIM 768
#define H 8
#define NEGV -1e10f
#define RS96 0.1020620726159658f  // 1/sqrt(96)
#define NI (B * S)                // 8192 total rows
#define DH 96                     // head dim

// ---------------------------------------------------------------------------
// Scratch (static device globals — allocation-free per harness rules)
// ---------------------------------------------------------------------------
__device__ float g_logit[NI];
__device__ float g_aw[NI];
__device__ float g_R[NI * H];
__device__ float g_T[B * H * DIM];
// bf16 hi/lo splits of inputs
__device__ __nv_bfloat16 g_Xhi[NI * DIM];
__device__ __nv_bfloat16 g_Xlo[NI * DIM];
__device__ __nv_bfloat16 g_Wqhi[DIM * DIM];
__device__ __nv_bfloat16 g_Wqlo[DIM * DIM];
__device__ __nv_bfloat16 g_Wkhi[DIM * DIM];
__device__ __nv_bfloat16 g_Wklo[DIM * DIM];
// head-packed projections: [h][i][d] bf16 hi/lo (RS96 folded into Q)
__device__ __nv_bfloat16 g_Qphi[H * NI * DH];
__device__ __nv_bfloat16 g_Qplo[H * NI * DH];
__device__ __nv_bfloat16 g_Kphi[H * NI * DH];
__device__ __nv_bfloat16 g_Kplo[H * NI * DH];

// ---------------------------------------------------------------------------
#define MMA16816(d, a0, a1, a2, a3, b0, b1)                                    \
    asm volatile("mma.sync.aligned.m16n8k16.row.col.f32.bf16.bf16.f32 "        \
                 "{%0,%1,%2,%3}, {%4,%5,%6,%7}, {%8,%9}, {%0,%1,%2,%3};"       \
                 : "+f"((d)[0]), "+f"((d)[1]), "+f"((d)[2]), "+f"((d)[3])      \
                 : "r"(a0), "r"(a1), "r"(a2), "r"(a3), "r"(b0), "r"(b1))

__device__ __forceinline__ uint32_t packbf2(__nv_bfloat16 a, __nv_bfloat16 b) {
    __nv_bfloat162 p(a, b);
    return *reinterpret_cast<uint32_t*>(&p);
}
__device__ __forceinline__ uint32_t smem_u32(const void* p) {
    uint32_t a;
    asm("{ .reg .u64 t; cvta.to.shared.u64 t, %1; cvt.u32.u64 %0, t; }"
        : "=r"(a) : "l"(p));
    return a;
}
__device__ __forceinline__ void cp16(uint32_t dst, const void* src) {
    asm volatile("cp.async.cg.shared.global [%0], [%1], 16;" :: "r"(dst), "l"(src));
}
#define CP_COMMIT() asm volatile("cp.async.commit_group;" ::: "memory")
#define CP_WAIT1() asm volatile("cp.async.wait_group 1;" ::: "memory")
#define CP_WAIT0() asm volatile("cp.async.wait_group 0;" ::: "memory")

// ---------------------------------------------------------------------------
__global__ void k0_zeroR() {
    int i = blockIdx.x * blockDim.x + threadIdx.x;
    if (i < NI * H) g_R[i] = 0.f;
}

// ---------------------------------------------------------------------------
// Ksplit: fp32 -> bf16 hi + bf16 lo. Destinations selected in device code
// (device symbols must never be host-side kernel args).
// ---------------------------------------------------------------------------
__global__ void ksplit_sel(const float* __restrict__ src, int which, int n4) {
    __nv_bfloat16 *hi, *lo;
    if (which == 0)      { hi = g_Xhi;  lo = g_Xlo;  }
    else if (which == 1) { hi = g_Wqhi; lo = g_Wqlo; }
    else                 { hi = g_Wkhi; lo = g_Wklo; }
    int i = blockIdx.x * blockDim.x + threadIdx.x;
    if (i >= n4) return;
    float4 v = ((const float4*)src)[i];
    __nv_bfloat16 h0 = __float2bfloat16(v.x), h1 = __float2bfloat16(v.y);
    __nv_bfloat16 h2 = __float2bfloat16(v.z), h3 = __float2bfloat16(v.w);
    __nv_bfloat16 l0 = __float2bfloat16(v.x - __bfloat162float(h0));
    __nv_bfloat16 l1 = __float2bfloat16(v.y - __bfloat162float(h1));
    __nv_bfloat16 l2 = __float2bfloat16(v.z - __bfloat162float(h2));
    __nv_bfloat16 l3 = __float2bfloat16(v.w - __bfloat162float(h3));
    ((__nv_bfloat162*)hi)[2 * i] = __nv_bfloat162(h0, h1);
    ((__nv_bfloat162*)hi)[2 * i + 1] = __nv_bfloat162(h2, h3);
    ((__nv_bfloat162*)lo)[2 * i] = __nv_bfloat162(l0, l1);
    ((__nv_bfloat162*)lo)[2 * i + 1] = __nv_bfloat162(l2, l3);
}

// ---------------------------------------------------------------------------
// K1a: span logits  l[i] = X[i,:] . w  (masked with NEG where tag==0)
// ---------------------------------------------------------------------------
__global__ void k1a_logits(const float* __restrict__ X,
                           const int* __restrict__ tags,
                           const float* __restrict__ w) {
    int warp = threadIdx.x >> 5, lane = threadIdx.x & 31;
    int row = blockIdx.x * 8 + warp;
    const float4* xr = (const float4*)(X + (size_t)row * DIM);
    const float4* wr = (const float4*)w;
    float s = 0.f;
#pragma unroll
    for (int i = 0; i < 6; i++) {
        float4 a = xr[lane + 32 * i];
        float4 b = wr[lane + 32 * i];
        s += a.x * b.x + a.y * b.y + a.z * b.z + a.w * b.w;
    }
#pragma unroll
    for (int o = 16; o; o >>= 1) s += __shfl_xor_sync(0xffffffffu, s, o);
    if (lane == 0) g_logit[row] = (tags[row] == 0) ? NEGV : s;
}

// ---------------------------------------------------------------------------
__global__ void k1b_softmax() {
    __shared__ float red[256];
    int b = blockIdx.x, t = threadIdx.x;
    float l[4];
#pragma unroll
    for (int i = 0; i < 4; i++) l[i] = g_logit[b * S + t + 256 * i];
    float mx = fmaxf(fmaxf(l[0], l[1]), fmaxf(l[2], l[3]));
    red[t] = mx;
    __syncthreads();
    for (int o = 128; o; o >>= 1) {
        if (t < o) red[t] = fmaxf(red[t], red[t + o]);
        __syncthreads();
    }
    mx = red[0];
    __syncthreads();
    float e[4], sum = 0.f;
#pragma unroll
    for (int i = 0; i < 4; i++) { e[i] = __expf(l[i] - mx); sum += e[i]; }
    red[t] = sum;
    __syncthreads();
    for (int o = 128; o; o >>= 1) {
        if (t < o) red[t] += red[t + o];
        __syncthreads();
    }
    float inv = 1.f / red[0];
#pragma unroll
    for (int i = 0; i < 4; i++) g_aw[b * S + t + 256 * i] = e[i] * inv;
}

// ---------------------------------------------------------------------------
// K2 (mma.sync bf16x3, VERIFIED math) + cp.async double-buffer pipeline.
// 72 flattened stages (3 terms x 24 k-chunks). Dynamic smem: 2 x 20480 B
// buffers; Cs epilogue overlays buffer 0.
// ---------------------------------------------------------------------------
#define K2_BUF 10240  // elems per buffer: As 128*40 + Bq 64*40 + Bk 64*40
__global__ void __launch_bounds__(256, 2) k2_mma() {
    extern __shared__ __align__(16) __nv_bfloat16 sm2[];
    float* Cs = (float*)sm2;  // [128][66] overlay (after mainloop)
    int t = threadIdx.x, l = t & 31, wid = t >> 5;
    int wm = wid & 3, wn = wid >> 2;
    int i0 = blockIdx.x * 128, j0 = blockIdx.y * 64;
    int lg = l >> 2;         // groupID 0..7
    int lk2 = 2 * (l & 3);   // k-pair base 0,2,4,6
    uint32_t sb = smem_u32(sm2);
    int ar = t >> 2, ac = (t & 3) * 8;

    float qacc[2][4][4], kacc[2][4][4];
#pragma unroll
    for (int am = 0; am < 2; am++)
#pragma unroll
        for (int bn = 0; bn < 4; bn++)
#pragma unroll
            for (int r = 0; r < 4; r++) { qacc[am][bn][r] = 0.f; kacc[am][bn][r] = 0.f; }

    // stage s: term = s/24 (0:hi*hi 1:lo*hi 2:hi*lo), kb = (s%24)*32
    auto issue = [&](int s) {
        const __nv_bfloat16* XA = (s >= 24 && s < 48) ? g_Xlo : g_Xhi;
        const __nv_bfloat16* WQ = (s < 48) ? g_Wqhi : g_Wqlo;
        const __nv_bfloat16* WK = (s < 48) ? g_Wkhi : g_Wklo;
        int kb = (s % 24) * 32;
        uint32_t base = sb + (uint32_t)(s & 1) * (K2_BUF * 2);
        cp16(base + (ar * 40 + ac) * 2, XA + (size_t)(i0 + ar) * DIM + kb + ac);
        cp16(base + ((ar + 64) * 40 + ac) * 2, XA + (size_t)(i0 + ar + 64) * DIM + kb + ac);
        cp16(base + (5120 + ar * 40 + ac) * 2, WQ + (size_t)(j0 + ar) * DIM + kb + ac);
        cp16(base + (7680 + ar * 40 + ac) * 2, WK + (size_t)(j0 + ar) * DIM + kb + ac);
    };

    issue(0);
    CP_COMMIT();
    for (int s = 0; s < 72; s++) {
        if (s < 71) { issue(s + 1); CP_COMMIT(); CP_WAIT1(); }
        else CP_WAIT0();
        __syncthreads();
        const __nv_bfloat16* As = sm2 + (s & 1) * K2_BUF;
        const __nv_bfloat16* Bq = As + 5120;
        const __nv_bfloat16* Bk = As + 7680;
#pragma unroll
        for (int kk = 0; kk < 2; kk++) {
            int ko = kk * 16;
            uint32_t a[2][4];
#pragma unroll
            for (int am = 0; am < 2; am++) {
                const __nv_bfloat16* ap = As + (wm * 32 + am * 16 + lg) * 40 + ko + lk2;
                a[am][0] = *(const uint32_t*)(ap);
                a[am][1] = *(const uint32_t*)(ap + 8 * 40);
                a[am][2] = *(const uint32_t*)(ap + 8);
                a[am][3] = *(const uint32_t*)(ap + 8 * 40 + 8);
            }
#pragma unroll
            for (int bp = 0; bp < 2; bp++)
#pragma unroll
                for (int o = 0; o < 2; o++) {
                    int nr = wn * 32 + bp * 16 + o * 8 + lg;
                    const __nv_bfloat16* bqp = Bq + nr * 40 + ko + lk2;
                    uint32_t q0 = *(const uint32_t*)(bqp);
                    uint32_t q1 = *(const uint32_t*)(bqp + 8);
                    MMA16816(qacc[0][2 * bp + o], a[0][0], a[0][1], a[0][2], a[0][3], q0, q1);
                    MMA16816(qacc[1][2 * bp + o], a[1][0], a[1][1], a[1][2], a[1][3], q0, q1);
                    const __nv_bfloat16* bkp = Bk + nr * 40 + ko + lk2;
                    uint32_t k0 = *(const uint32_t*)(bkp);
                    uint32_t k1 = *(const uint32_t*)(bkp + 8);
                    MMA16816(kacc[0][2 * bp + o], a[0][0], a[0][1], a[0][2], a[0][3], k0, k1);
                    MMA16816(kacc[1][2 * bp + o], a[1][0], a[1][1], a[1][2], a[1][3], k0, k1);
                }
        }
        __syncthreads();
    }

    int d0 = j0 >> 3;
    // ---- Q pass (RS96 folded) ----
#pragma unroll
    for (int am = 0; am < 2; am++)
#pragma unroll
        for (int bn = 0; bn < 4; bn++) {
            int r0 = wm * 32 + am * 16 + lg;
            int c = wn * 32 + bn * 8 + lk2;
            Cs[r0 * 66 + c] = qacc[am][bn][0];
            Cs[r0 * 66 + c + 1] = qacc[am][bn][1];
            Cs[(r0 + 8) * 66 + c] = qacc[am][bn][2];
            Cs[(r0 + 8) * 66 + c + 1] = qacc[am][bn][3];
        }
    __syncthreads();
#pragma unroll
    for (int u = 0; u < 4; u++) {
        int rowid = t + 256 * u;
        int h = rowid & 7, i = rowid >> 3;
        uint4 hv, lv;
        uint32_t* hp = (uint32_t*)&hv;
        uint32_t* lp = (uint32_t*)&lv;
#pragma unroll
        for (int dd = 0; dd < 4; dd++) {
            float v0 = Cs[i * 66 + h + 8 * (2 * dd)] * RS96;
            float v1 = Cs[i * 66 + h + 8 * (2 * dd + 1)] * RS96;
            __nv_bfloat16 h0 = __float2bfloat16(v0), h1 = __float2bfloat16(v1);
            __nv_bfloat16 l0 = __float2bfloat16(v0 - __bfloat162float(h0));
            __nv_bfloat16 l1 = __float2bfloat16(v1 - __bfloat162float(h1));
            hp[dd] = packbf2(h0, h1);
            lp[dd] = packbf2(l0, l1);
        }
        size_t off = ((size_t)h * NI + i0 + i) * DH + d0;
        *(uint4*)(g_Qphi + off) = hv;
        *(uint4*)(g_Qplo + off) = lv;
    }
    // ---- K pass ----
    __syncthreads();
#pragma unroll
    for (int am = 0; am < 2; am++)
#pragma unroll
        for (int bn = 0; bn < 4; bn++) {
            int r0 = wm * 32 + am * 16 + lg;
            int c = wn * 32 + bn * 8 + lk2;
            Cs[r0 * 66 + c] = kacc[am][bn][0];
            Cs[r0 * 66 + c + 1] = kacc[am][bn][1];
            Cs[(r0 + 8) * 66 + c] = kacc[am][bn][2];
            Cs[(r0 + 8) * 66 + c + 1] = kacc[am][bn][3];
        }
    __syncthreads();
#pragma unroll
    for (int u = 0; u < 4; u++) {
        int rowid = t + 256 * u;
        int h = rowid & 7, i = rowid >> 3;
        uint4 hv, lv;
        uint32_t* hp = (uint32_t*)&hv;
        uint32_t* lp = (uint32_t*)&lv;
#pragma unroll
        for (int dd = 0; dd < 4; dd++) {
            float v0 = Cs[i * 66 + h + 8 * (2 * dd)];
            float v1 = Cs[i * 66 + h + 8 * (2 * dd + 1)];
            __nv_bfloat16 h0 = __float2bfloat16(v0), h1 = __float2bfloat16(v1);
            __nv_bfloat16 l0 = __float2bfloat16(v0 - __bfloat162float(h0));
            __nv_bfloat16 l1 = __float2bfloat16(v1 - __bfloat162float(h1));
            hp[dd] = packbf2(h0, h1);
            lp[dd] = packbf2(l0, l1);
        }
        size_t off = ((size_t)h * NI + i0 + i) * DH + d0;
        *(uint4*)(g_Kphi + off) = hv;
        *(uint4*)(g_Kplo + off) = lv;
    }
}

// ---------------------------------------------------------------------------
// K3 (mma.sync bf16x3, VERIFIED math) + cp.async double-buffer pipeline.
// q64 x k64, 512 threads, 16 warps (4q x 4k); 6 d16 stages; 2 x 4-tile
// buffers = 192 KB dynamic smem.
// ---------------------------------------------------------------------------
#define K3_TILE (8 * 64 * 24)
__global__ void __launch_bounds__(512, 1) k3_attn() {
    extern __shared__ __align__(16) __nv_bfloat16 sm3[];
    __shared__ float Rs[64][8];
    int b = blockIdx.z, q0 = blockIdx.y * 64, k0 = blockIdx.x * 64;
    int t = threadIdx.x, l = t & 31, wid = t >> 5;
    int wq = wid & 3, wk = wid >> 2;  // 4q x 4k
    int lg = l >> 2, lk2 = 2 * (l & 3);
    int iq = b * S + q0, ik = b * S + k0;
    uint32_t sb = smem_u32(sm3);
    ((float*)Rs)[t] = 0.f;

    float acc[8][2][4];
#pragma unroll
    for (int h = 0; h < 8; h++)
#pragma unroll
        for (int bn = 0; bn < 2; bn++)
#pragma unroll
            for (int r = 0; r < 4; r++) acc[h][bn][r] = 0.f;

    int lh = t >> 6, lrow = t & 63;
    size_t qoff = ((size_t)lh * NI + iq + lrow) * DH;
    size_t koff = ((size_t)lh * NI + ik + lrow) * DH;

    auto issue = [&](int s) {
        int dd0 = s * 16;
        uint32_t base = sb + (uint32_t)(s & 1) * (4 * K3_TILE * 2);
        uint32_t ro = (uint32_t)t * 48;  // t*24 elems * 2B
        cp16(base + ro, g_Qphi + qoff + dd0);
        cp16(base + ro + 16, g_Qphi + qoff + dd0 + 8);
        cp16(base + K3_TILE * 2 + ro, g_Qplo + qoff + dd0);
        cp16(base + K3_TILE * 2 + ro + 16, g_Qplo + qoff + dd0 + 8);
        cp16(base + K3_TILE * 4 + ro, g_Kphi + koff + dd0);
        cp16(base + K3_TILE * 4 + ro + 16, g_Kphi + koff + dd0 + 8);
        cp16(base + K3_TILE * 6 + ro, g_Kplo + koff + dd0);
        cp16(base + K3_TILE * 6 + ro + 16, g_Kplo + koff + dd0 + 8);
    };

    issue(0);
    CP_COMMIT();
    for (int s = 0; s < 6; s++) {
        if (s < 5) { issue(s + 1); CP_COMMIT(); CP_WAIT1(); }
        else CP_WAIT0();
        __syncthreads();
        const __nv_bfloat16* Qh = sm3 + (s & 1) * 4 * K3_TILE;
        const __nv_bfloat16* Ql = Qh + K3_TILE;
        const __nv_bfloat16* Kh = Ql + K3_TILE;
        const __nv_bfloat16* Kl = Kh + K3_TILE;
#pragma unroll
        for (int h = 0; h < 8; h++) {
            int arow = (h * 64 + wq * 16 + lg) * 24 + lk2;
            const __nv_bfloat16* aph = Qh + arow;
            uint32_t ah0 = *(const uint32_t*)(aph);
            uint32_t ah1 = *(const uint32_t*)(aph + 8 * 24);
            uint32_t ah2 = *(const uint32_t*)(aph + 8);
            uint32_t ah3 = *(const uint32_t*)(aph + 8 * 24 + 8);
            const __nv_bfloat16* apl = Ql + arow;
            uint32_t al0 = *(const uint32_t*)(apl);
            uint32_t al1 = *(const uint32_t*)(apl + 8 * 24);
            uint32_t al2 = *(const uint32_t*)(apl + 8);
            uint32_t al3 = *(const uint32_t*)(apl + 8 * 24 + 8);
#pragma unroll
            for (int o = 0; o < 2; o++) {
                int brow = (h * 64 + wk * 16 + o * 8 + lg) * 24 + lk2;
                const __nv_bfloat16* bph = Kh + brow;
                uint32_t bh0 = *(const uint32_t*)(bph);
                uint32_t bh1 = *(const uint32_t*)(bph + 8);
                const __nv_bfloat16* bpl = Kl + brow;
                uint32_t bl0 = *(const uint32_t*)(bpl);
                uint32_t bl1 = *(const uint32_t*)(bpl + 8);
                MMA16816(acc[h][o], ah0, ah1, ah2, ah3, bh0, bh1);  // hi.hi
                MMA16816(acc[h][o], al0, al1, al2, al3, bh0, bh1);  // lo.hi
                MMA16816(acc[h][o], ah0, ah1, ah2, ah3, bl0, bl1);  // hi.lo
            }
        }
        __syncthreads();
    }

    // Epilogue (verified): softmax over h, aw-weighted q-reduction.
    float aw0 = g_aw[iq + wq * 16 + lg];
    float aw1 = g_aw[iq + wq * 16 + lg + 8];
#pragma unroll
    for (int bn = 0; bn < 2; bn++) {
        float rk[2][8];
#pragma unroll
        for (int ci = 0; ci < 2; ci++)
#pragma unroll
            for (int h = 0; h < 8; h++) rk[ci][h] = 0.f;
#pragma unroll
        for (int ci = 0; ci < 2; ci++)
#pragma unroll
            for (int ri = 0; ri < 2; ri++) {
                float aw = ri ? aw1 : aw0;
                float v[8];
#pragma unroll
                for (int h = 0; h < 8; h++) v[h] = acc[h][bn][ri * 2 + ci];
                float m = v[0];
#pragma unroll
                for (int h = 1; h < 8; h++) m = fmaxf(m, v[h]);
                float e[8], s = 0.f;
#pragma unroll
                for (int h = 0; h < 8; h++) { e[h] = __expf(v[h] - m); s += e[h]; }
                float w = __fdividef(aw, s);
#pragma unroll
                for (int h = 0; h < 8; h++) rk[ci][h] += w * e[h];
            }
#pragma unroll
        for (int ci = 0; ci < 2; ci++)
#pragma unroll
            for (int h = 0; h < 8; h++) {
                float r = rk[ci][h];
                r += __shfl_xor_sync(0xffffffffu, r, 4);
                r += __shfl_xor_sync(0xffffffffu, r, 8);
                r += __shfl_xor_sync(0xffffffffu, r, 16);
                if (l < 4) {
                    int kl = wk * 16 + bn * 8 + 2 * l + ci;
                    atomicAdd(&Rs[kl][h], r);
                }
            }
    }
    __syncthreads();
    atomicAdd(&g_R[(size_t)(ik + (t >> 3)) * H + (t & 7)], Rs[t >> 3][t & 7]);
}

// ---------------------------------------------------------------------------
// K4: T[b,h,m] = sum_k R[b,k,h] * X[b,k,m]
// ---------------------------------------------------------------------------
__global__ void __launch_bounds__(256) k4_T(const float* __restrict__ X) {
    __shared__ float Xs[64][64];
    __shared__ float Rsm[64][8];
    int b = blockIdx.y;
    int m0 = blockIdx.x * 64;
    int t = threadIdx.x;
    int m = t & 63, hh = t >> 6;
    float acc0 = 0.f, acc1 = 0.f;
    for (int kc = 0; kc < S; kc += 64) {
#pragma unroll
        for (int u = 0; u < 4; u++) {
            int lin = t + 256 * u;
            int r = lin >> 4, c = (lin & 15) << 2;
            *(float4*)&Xs[r][c] =
                *(const float4*)(X + (size_t)(b * S + kc + r) * DIM + m0 + c);
        }
        {
            float2 v = *(const float2*)(g_R + ((size_t)b * S + kc) * H + t * 2);
            *(float2*)&((float*)Rsm)[t * 2] = v;
        }
        __syncthreads();
#pragma unroll 8
        for (int k = 0; k < 64; k++) {
            float x = Xs[k][m];
            acc0 += Rsm[k][hh] * x;
            acc1 += Rsm[k][hh + 4] * x;
        }
        __syncthreads();
    }
    g_T[((size_t)b * H + hh) * DIM + m0 + m] = acc0;
    g_T[((size_t)b * H + hh + 4) * DIM + m0 + m] = acc1;
}

// ---------------------------------------------------------------------------
// K5: out[b,j] = sum_m Wv[j,m] * T[b, j&7, m]
// ---------------------------------------------------------------------------
__global__ void k5_out(const float* __restrict__ Wv, float* __restrict__ out) {
    int warp = threadIdx.x >> 5, lane = threadIdx.x & 31;
    int g = blockIdx.x * 8 + warp;
    int b = g / DIM, j = g % DIM;
    int h = j & 7;
    const float4* wr = (const float4*)(Wv + (size_t)j * DIM);
    const float4* tr = (const float4*)(g_T + ((size_t)b * H + h) * DIM);
    float s = 0.f;
#pragma unroll
    for (int i = 0; i < 6; i++) {
        float4 a = wr[lane + 32 * i];
        float4 c = tr[lane + 32 * i];
        s += a.x * c.x + a.y * c.y + a.z * c.z + a.w * c.w;
    }
#pragma unroll
    for (int o = 16; o; o >>= 1) s += __shfl_xor_sync(0xffffffffu, s, o);
    if (lane == 0) out[(size_t)b * DIM + j] = s;
}

// ---------------------------------------------------------------------------
extern "C" void kernel_launch(void* const* d_in, const int* in_sizes, int n_in,
                              void* d_out, int out_size) {
    const float* X    = (const float*)d_in[0];
    const int*   tags = (const int*)d_in[1];
    const float* w    = (const float*)d_in[2];
    const float* Wq   = (const float*)d_in[3];
    const float* Wk   = (const float*)d_in[4];
    const float* Wv   = (const float*)d_in[5];
    float* out = (float*)d_out;

    static int attr_set = 0;
    if (!attr_set) {
        cudaFuncSetAttribute(k3_attn, cudaFuncAttributeMaxDynamicSharedMemorySize,
                             8 * K3_TILE * (int)sizeof(__nv_bfloat16));  // 192 KB
        attr_set = 1;
    }

    k0_zeroR<<<(NI * H + 255) / 256, 256>>>();
    ksplit_sel<<<(NI * DIM / 4 + 255) / 256, 256>>>(X, 0, NI * DIM / 4);
    ksplit_sel<<<(DIM * DIM / 4 + 255) / 256, 256>>>(Wq, 1, DIM * DIM / 4);
    ksplit_sel<<<(DIM * DIM / 4 + 255) / 256, 256>>>(Wk, 2, DIM * DIM / 4);
    k1a_logits<<<NI / 8, 256>>>(X, tags, w);
    k1b_softmax<<<B, 256>>>();
    k2_mma<<<dim3(64, 12), 256, 2 * K2_BUF * sizeof(__nv_bfloat16)>>>();
    k3_attn<<<dim3(16, 16, 8), 512, 8 * K3_TILE * sizeof(__nv_bfloat16)>>>();
    k4_T<<<dim3(12, 8), 256>>>(X);
    k5_out<<<768, 256>>>(Wv, out);
}

// round 16
// speedup vs baseline: 1.4045x; 1.0226x over previous
#include <cuda_runtime.h>
#include <cuda_bf16.h>
#include <cstdint>

#define B 8
#define S 1024
#define DIM 768
#define H 8
#define NEGV -1e10f
#define RS96 0.1020620726159658f  // 1/sqrt(96)
#define NI (B * S)                // 8192 total rows
#define DH 96                     // head dim

// ---------------------------------------------------------------------------
// Scratch (static device globals — allocation-free per harness rules)
// ---------------------------------------------------------------------------
__device__ float g_logit[NI];
__device__ float g_aw[NI];
__device__ float g_R[NI * H];
__device__ float g_T[B * H * DIM];
// bf16 hi/lo splits of inputs
__device__ __nv_bfloat16 g_Xhi[NI * DIM];
__device__ __nv_bfloat16 g_Xlo[NI * DIM];
__device__ __nv_bfloat16 g_Wqhi[DIM * DIM];
__device__ __nv_bfloat16 g_Wqlo[DIM * DIM];
__device__ __nv_bfloat16 g_Wkhi[DIM * DIM];
__device__ __nv_bfloat16 g_Wklo[DIM * DIM];
// head-packed projections: [h][i][d] bf16 hi/lo (RS96 folded into Q)
__device__ __nv_bfloat16 g_Qphi[H * NI * DH];
__device__ __nv_bfloat16 g_Qplo[H * NI * DH];
__device__ __nv_bfloat16 g_Kphi[H * NI * DH];
__device__ __nv_bfloat16 g_Kplo[H * NI * DH];

// ---------------------------------------------------------------------------
#define MMA16816(d, a0, a1, a2, a3, b0, b1)                                    \
    asm volatile("mma.sync.aligned.m16n8k16.row.col.f32.bf16.bf16.f32 "        \
                 "{%0,%1,%2,%3}, {%4,%5,%6,%7}, {%8,%9}, {%0,%1,%2,%3};"       \
                 : "+f"((d)[0]), "+f"((d)[1]), "+f"((d)[2]), "+f"((d)[3])      \
                 : "r"(a0), "r"(a1), "r"(a2), "r"(a3), "r"(b0), "r"(b1))

#define LDSM4(r0, r1, r2, r3, addr)                                            \
    asm volatile("ldmatrix.sync.aligned.m8n8.x4.shared.b16 {%0,%1,%2,%3}, [%4];" \
                 : "=r"(r0), "=r"(r1), "=r"(r2), "=r"(r3) : "r"(addr))

__device__ __forceinline__ uint32_t packbf2(__nv_bfloat16 a, __nv_bfloat16 b) {
    __nv_bfloat162 p(a, b);
    return *reinterpret_cast<uint32_t*>(&p);
}
__device__ __forceinline__ uint32_t smem_u32(const void* p) {
    uint32_t a;
    asm("{ .reg .u64 t; cvta.to.shared.u64 t, %1; cvt.u32.u64 %0, t; }"
        : "=r"(a) : "l"(p));
    return a;
}
__device__ __forceinline__ void cp16(uint32_t dst, const void* src) {
    asm volatile("cp.async.cg.shared.global [%0], [%1], 16;" :: "r"(dst), "l"(src));
}
#define CP_COMMIT() asm volatile("cp.async.commit_group;" ::: "memory")
#define CP_WAIT1() asm volatile("cp.async.wait_group 1;" ::: "memory")
#define CP_WAIT0() asm volatile("cp.async.wait_group 0;" ::: "memory")

// ---------------------------------------------------------------------------
__global__ void k0_zeroR() {
    int i = blockIdx.x * blockDim.x + threadIdx.x;
    if (i < NI * H) g_R[i] = 0.f;
}

// ---------------------------------------------------------------------------
// Ksplit: fp32 -> bf16 hi + bf16 lo. Destinations selected in device code
// (device symbols must never be host-side kernel args).
// ---------------------------------------------------------------------------
__global__ void ksplit_sel(const float* __restrict__ src, int which, int n4) {
    __nv_bfloat16 *hi, *lo;
    if (which == 0)      { hi = g_Xhi;  lo = g_Xlo;  }
    else if (which == 1) { hi = g_Wqhi; lo = g_Wqlo; }
    else                 { hi = g_Wkhi; lo = g_Wklo; }
    int i = blockIdx.x * blockDim.x + threadIdx.x;
    if (i >= n4) return;
    float4 v = ((const float4*)src)[i];
    __nv_bfloat16 h0 = __float2bfloat16(v.x), h1 = __float2bfloat16(v.y);
    __nv_bfloat16 h2 = __float2bfloat16(v.z), h3 = __float2bfloat16(v.w);
    __nv_bfloat16 l0 = __float2bfloat16(v.x - __bfloat162float(h0));
    __nv_bfloat16 l1 = __float2bfloat16(v.y - __bfloat162float(h1));
    __nv_bfloat16 l2 = __float2bfloat16(v.z - __bfloat162float(h2));
    __nv_bfloat16 l3 = __float2bfloat16(v.w - __bfloat162float(h3));
    ((__nv_bfloat162*)hi)[2 * i] = __nv_bfloat162(h0, h1);
    ((__nv_bfloat162*)hi)[2 * i + 1] = __nv_bfloat162(h2, h3);
    ((__nv_bfloat162*)lo)[2 * i] = __nv_bfloat162(l0, l1);
    ((__nv_bfloat162*)lo)[2 * i + 1] = __nv_bfloat162(l2, l3);
}

// ---------------------------------------------------------------------------
// K1a: span logits  l[i] = X[i,:] . w  (masked with NEG where tag==0)
// ---------------------------------------------------------------------------
__global__ void k1a_logits(const float* __restrict__ X,
                           const int* __restrict__ tags,
                           const float* __restrict__ w) {
    int warp = threadIdx.x >> 5, lane = threadIdx.x & 31;
    int row = blockIdx.x * 8 + warp;
    const float4* xr = (const float4*)(X + (size_t)row * DIM);
    const float4* wr = (const float4*)w;
    float s = 0.f;
#pragma unroll
    for (int i = 0; i < 6; i++) {
        float4 a = xr[lane + 32 * i];
        float4 b = wr[lane + 32 * i];
        s += a.x * b.x + a.y * b.y + a.z * b.z + a.w * b.w;
    }
#pragma unroll
    for (int o = 16; o; o >>= 1) s += __shfl_xor_sync(0xffffffffu, s, o);
    if (lane == 0) g_logit[row] = (tags[row] == 0) ? NEGV : s;
}

// ---------------------------------------------------------------------------
__global__ void k1b_softmax() {
    __shared__ float red[256];
    int b = blockIdx.x, t = threadIdx.x;
    float l[4];
#pragma unroll
    for (int i = 0; i < 4; i++) l[i] = g_logit[b * S + t + 256 * i];
    float mx = fmaxf(fmaxf(l[0], l[1]), fmaxf(l[2], l[3]));
    red[t] = mx;
    __syncthreads();
    for (int o = 128; o; o >>= 1) {
        if (t < o) red[t] = fmaxf(red[t], red[t + o]);
        __syncthreads();
    }
    mx = red[0];
    __syncthreads();
    float e[4], sum = 0.f;
#pragma unroll
    for (int i = 0; i < 4; i++) { e[i] = __expf(l[i] - mx); sum += e[i]; }
    red[t] = sum;
    __syncthreads();
    for (int o = 128; o; o >>= 1) {
        if (t < o) red[t] += red[t + o];
        __syncthreads();
    }
    float inv = 1.f / red[0];
#pragma unroll
    for (int i = 0; i < 4; i++) g_aw[b * S + t + 256 * i] = e[i] * inv;
}

// ---------------------------------------------------------------------------
// K2 (mma.sync bf16x3, VERIFIED math) + cp.async double-buffer pipeline.
// 72 flattened stages (3 terms x 24 k-chunks). Dynamic smem: 2 x 20480 B
// buffers; Cs epilogue overlays buffer 0.
// ---------------------------------------------------------------------------
#define K2_BUF 10240  // elems per buffer: As 128*40 + Bq 64*40 + Bk 64*40
__global__ void __launch_bounds__(256, 2) k2_mma() {
    extern __shared__ __align__(16) __nv_bfloat16 sm2[];
    float* Cs = (float*)sm2;  // [128][66] overlay (after mainloop)
    int t = threadIdx.x, l = t & 31, wid = t >> 5;
    int wm = wid & 3, wn = wid >> 2;
    int i0 = blockIdx.x * 128, j0 = blockIdx.y * 64;
    int lg = l >> 2;         // groupID 0..7
    int lk2 = 2 * (l & 3);   // k-pair base 0,2,4,6
    uint32_t sb = smem_u32(sm2);
    int ar = t >> 2, ac = (t & 3) * 8;

    float qacc[2][4][4], kacc[2][4][4];
#pragma unroll
    for (int am = 0; am < 2; am++)
#pragma unroll
        for (int bn = 0; bn < 4; bn++)
#pragma unroll
            for (int r = 0; r < 4; r++) { qacc[am][bn][r] = 0.f; kacc[am][bn][r] = 0.f; }

    // stage s: term = s/24 (0:hi*hi 1:lo*hi 2:hi*lo), kb = (s%24)*32
    auto issue = [&](int s) {
        const __nv_bfloat16* XA = (s >= 24 && s < 48) ? g_Xlo : g_Xhi;
        const __nv_bfloat16* WQ = (s < 48) ? g_Wqhi : g_Wqlo;
        const __nv_bfloat16* WK = (s < 48) ? g_Wkhi : g_Wklo;
        int kb = (s % 24) * 32;
        uint32_t base = sb + (uint32_t)(s & 1) * (K2_BUF * 2);
        cp16(base + (ar * 40 + ac) * 2, XA + (size_t)(i0 + ar) * DIM + kb + ac);
        cp16(base + ((ar + 64) * 40 + ac) * 2, XA + (size_t)(i0 + ar + 64) * DIM + kb + ac);
        cp16(base + (5120 + ar * 40 + ac) * 2, WQ + (size_t)(j0 + ar) * DIM + kb + ac);
        cp16(base + (7680 + ar * 40 + ac) * 2, WK + (size_t)(j0 + ar) * DIM + kb + ac);
    };

    issue(0);
    CP_COMMIT();
    for (int s = 0; s < 72; s++) {
        if (s < 71) { issue(s + 1); CP_COMMIT(); CP_WAIT1(); }
        else CP_WAIT0();
        __syncthreads();
        const __nv_bfloat16* As = sm2 + (s & 1) * K2_BUF;
        const __nv_bfloat16* Bq = As + 5120;
        const __nv_bfloat16* Bk = As + 7680;
#pragma unroll
        for (int kk = 0; kk < 2; kk++) {
            int ko = kk * 16;
            uint32_t a[2][4];
#pragma unroll
            for (int am = 0; am < 2; am++) {
                const __nv_bfloat16* ap = As + (wm * 32 + am * 16 + lg) * 40 + ko + lk2;
                a[am][0] = *(const uint32_t*)(ap);
                a[am][1] = *(const uint32_t*)(ap + 8 * 40);
                a[am][2] = *(const uint32_t*)(ap + 8);
                a[am][3] = *(const uint32_t*)(ap + 8 * 40 + 8);
            }
#pragma unroll
            for (int bp = 0; bp < 2; bp++)
#pragma unroll
                for (int o = 0; o < 2; o++) {
                    int nr = wn * 32 + bp * 16 + o * 8 + lg;
                    const __nv_bfloat16* bqp = Bq + nr * 40 + ko + lk2;
                    uint32_t q0 = *(const uint32_t*)(bqp);
                    uint32_t q1 = *(const uint32_t*)(bqp + 8);
                    MMA16816(qacc[0][2 * bp + o], a[0][0], a[0][1], a[0][2], a[0][3], q0, q1);
                    MMA16816(qacc[1][2 * bp + o], a[1][0], a[1][1], a[1][2], a[1][3], q0, q1);
                    const __nv_bfloat16* bkp = Bk + nr * 40 + ko + lk2;
                    uint32_t k0 = *(const uint32_t*)(bkp);
                    uint32_t k1 = *(const uint32_t*)(bkp + 8);
                    MMA16816(kacc[0][2 * bp + o], a[0][0], a[0][1], a[0][2], a[0][3], k0, k1);
                    MMA16816(kacc[1][2 * bp + o], a[1][0], a[1][1], a[1][2], a[1][3], k0, k1);
                }
        }
        __syncthreads();
    }

    int d0 = j0 >> 3;
    // ---- Q pass (RS96 folded) ----
#pragma unroll
    for (int am = 0; am < 2; am++)
#pragma unroll
        for (int bn = 0; bn < 4; bn++) {
            int r0 = wm * 32 + am * 16 + lg;
            int c = wn * 32 + bn * 8 + lk2;
            Cs[r0 * 66 + c] = qacc[am][bn][0];
            Cs[r0 * 66 + c + 1] = qacc[am][bn][1];
            Cs[(r0 + 8) * 66 + c] = qacc[am][bn][2];
            Cs[(r0 + 8) * 66 + c + 1] = qacc[am][bn][3];
        }
    __syncthreads();
#pragma unroll
    for (int u = 0; u < 4; u++) {
        int rowid = t + 256 * u;
        int h = rowid & 7, i = rowid >> 3;
        uint4 hv, lv;
        uint32_t* hp = (uint32_t*)&hv;
        uint32_t* lp = (uint32_t*)&lv;
#pragma unroll
        for (int dd = 0; dd < 4; dd++) {
            float v0 = Cs[i * 66 + h + 8 * (2 * dd)] * RS96;
            float v1 = Cs[i * 66 + h + 8 * (2 * dd + 1)] * RS96;
            __nv_bfloat16 h0 = __float2bfloat16(v0), h1 = __float2bfloat16(v1);
            __nv_bfloat16 l0 = __float2bfloat16(v0 - __bfloat162float(h0));
            __nv_bfloat16 l1 = __float2bfloat16(v1 - __bfloat162float(h1));
            hp[dd] = packbf2(h0, h1);
            lp[dd] = packbf2(l0, l1);
        }
        size_t off = ((size_t)h * NI + i0 + i) * DH + d0;
        *(uint4*)(g_Qphi + off) = hv;
        *(uint4*)(g_Qplo + off) = lv;
    }
    // ---- K pass ----
    __syncthreads();
#pragma unroll
    for (int am = 0; am < 2; am++)
#pragma unroll
        for (int bn = 0; bn < 4; bn++) {
            int r0 = wm * 32 + am * 16 + lg;
            int c = wn * 32 + bn * 8 + lk2;
            Cs[r0 * 66 + c] = kacc[am][bn][0];
            Cs[r0 * 66 + c + 1] = kacc[am][bn][1];
            Cs[(r0 + 8) * 66 + c] = kacc[am][bn][2];
            Cs[(r0 + 8) * 66 + c + 1] = kacc[am][bn][3];
        }
    __syncthreads();
#pragma unroll
    for (int u = 0; u < 4; u++) {
        int rowid = t + 256 * u;
        int h = rowid & 7, i = rowid >> 3;
        uint4 hv, lv;
        uint32_t* hp = (uint32_t*)&hv;
        uint32_t* lp = (uint32_t*)&lv;
#pragma unroll
        for (int dd = 0; dd < 4; dd++) {
            float v0 = Cs[i * 66 + h + 8 * (2 * dd)];
            float v1 = Cs[i * 66 + h + 8 * (2 * dd + 1)];
            __nv_bfloat16 h0 = __float2bfloat16(v0), h1 = __float2bfloat16(v1);
            __nv_bfloat16 l0 = __float2bfloat16(v0 - __bfloat162float(h0));
            __nv_bfloat16 l1 = __float2bfloat16(v1 - __bfloat162float(h1));
            hp[dd] = packbf2(h0, h1);
            lp[dd] = packbf2(l0, l1);
        }
        size_t off = ((size_t)h * NI + i0 + i) * DH + d0;
        *(uint4*)(g_Kphi + off) = hv;
        *(uint4*)(g_Kplo + off) = lv;
    }
}

// ---------------------------------------------------------------------------
// K3 (mma.sync bf16x3, VERIFIED math) + cp.async pipeline + ldmatrix.x4
// fragment loads (4 LDSM per head replace 16 LDS.32).
// q64 x k64, 512 threads, 16 warps (4q x 4k); 6 d16 stages; 192 KB smem.
// ---------------------------------------------------------------------------
#define K3_TILE (8 * 64 * 24)
__global__ void __launch_bounds__(512, 1) k3_attn() {
    extern __shared__ __align__(16) __nv_bfloat16 sm3[];
    __shared__ float Rs[64][8];
    int b = blockIdx.z, q0 = blockIdx.y * 64, k0 = blockIdx.x * 64;
    int t = threadIdx.x, l = t & 31, wid = t >> 5;
    int wq = wid & 3, wk = wid >> 2;  // 4q x 4k
    int lg = l >> 2;
    int iq = b * S + q0, ik = b * S + k0;
    uint32_t sb = smem_u32(sm3);
    ((float*)Rs)[t] = 0.f;

    float acc[8][2][4];
#pragma unroll
    for (int h = 0; h < 8; h++)
#pragma unroll
        for (int bn = 0; bn < 2; bn++)
#pragma unroll
            for (int r = 0; r < 4; r++) acc[h][bn][r] = 0.f;

    int lh = t >> 6, lrow = t & 63;
    size_t qoff = ((size_t)lh * NI + iq + lrow) * DH;
    size_t koff = ((size_t)lh * NI + ik + lrow) * DH;

    // ldmatrix per-lane source offsets (elements) within a [64][24] head tile.
    // A (x4): m0 rows 0-7 k0-7, m1 rows 8-15 k0-7, m2 rows 0-7 k8-15,
    //         m3 rows 8-15 k8-15  -> frags a0..a3 of m16n8k16.
    // B (x4): m0 n0-7 k0-7 (b0,o=0), m1 n0-7 k8-15 (b1,o=0),
    //         m2 n8-15 k0-7 (b0,o=1), m3 n8-15 k8-15 (b1,o=1).
    int lrow8 = l & 7, sel = l >> 3;
    uint32_t offA = (uint32_t)((wq * 16 + (sel & 1) * 8 + lrow8) * 24 + (sel >> 1) * 8);
    uint32_t offB = (uint32_t)((wk * 16 + (sel >> 1) * 8 + lrow8) * 24 + (sel & 1) * 8);

    auto issue = [&](int s) {
        int dd0 = s * 16;
        uint32_t base = sb + (uint32_t)(s & 1) * (4 * K3_TILE * 2);
        uint32_t ro = (uint32_t)t * 48;  // t*24 elems * 2B
        cp16(base + ro, g_Qphi + qoff + dd0);
        cp16(base + ro + 16, g_Qphi + qoff + dd0 + 8);
        cp16(base + K3_TILE * 2 + ro, g_Qplo + qoff + dd0);
        cp16(base + K3_TILE * 2 + ro + 16, g_Qplo + qoff + dd0 + 8);
        cp16(base + K3_TILE * 4 + ro, g_Kphi + koff + dd0);
        cp16(base + K3_TILE * 4 + ro + 16, g_Kphi + koff + dd0 + 8);
        cp16(base + K3_TILE * 6 + ro, g_Kplo + koff + dd0);
        cp16(base + K3_TILE * 6 + ro + 16, g_Kplo + koff + dd0 + 8);
    };

    issue(0);
    CP_COMMIT();
    for (int s = 0; s < 6; s++) {
        if (s < 5) { issue(s + 1); CP_COMMIT(); CP_WAIT1(); }
        else CP_WAIT0();
        __syncthreads();
        uint32_t qh_b = sb + (uint32_t)(s & 1) * (4 * K3_TILE * 2);
        uint32_t ql_b = qh_b + K3_TILE * 2;
        uint32_t kh_b = qh_b + K3_TILE * 4;
        uint32_t kl_b = qh_b + K3_TILE * 6;
#pragma unroll
        for (int h = 0; h < 8; h++) {
            uint32_t ho = (uint32_t)(h * 64 * 24) * 2;
            uint32_t ah0, ah1, ah2, ah3, al0, al1, al2, al3;
            LDSM4(ah0, ah1, ah2, ah3, qh_b + ho + offA * 2);
            LDSM4(al0, al1, al2, al3, ql_b + ho + offA * 2);
            uint32_t bh0, bh1, bh2, bh3, bl0, bl1, bl2, bl3;
            LDSM4(bh0, bh1, bh2, bh3, kh_b + ho + offB * 2);
            LDSM4(bl0, bl1, bl2, bl3, kl_b + ho + offB * 2);
            // o = 0: B frags (bh0,bh1)/(bl0,bl1); o = 1: (bh2,bh3)/(bl2,bl3)
            MMA16816(acc[h][0], ah0, ah1, ah2, ah3, bh0, bh1);  // hi.hi
            MMA16816(acc[h][0], al0, al1, al2, al3, bh0, bh1);  // lo.hi
            MMA16816(acc[h][0], ah0, ah1, ah2, ah3, bl0, bl1);  // hi.lo
            MMA16816(acc[h][1], ah0, ah1, ah2, ah3, bh2, bh3);
            MMA16816(acc[h][1], al0, al1, al2, al3, bh2, bh3);
            MMA16816(acc[h][1], ah0, ah1, ah2, ah3, bl2, bl3);
        }
        __syncthreads();
    }

    // Epilogue (verified): softmax over h, aw-weighted q-reduction.
    float aw0 = g_aw[iq + wq * 16 + lg];
    float aw1 = g_aw[iq + wq * 16 + lg + 8];
#pragma unroll
    for (int bn = 0; bn < 2; bn++) {
        float rk[2][8];
#pragma unroll
        for (int ci = 0; ci < 2; ci++)
#pragma unroll
            for (int h = 0; h < 8; h++) rk[ci][h] = 0.f;
#pragma unroll
        for (int ci = 0; ci < 2; ci++)
#pragma unroll
            for (int ri = 0; ri < 2; ri++) {
                float aw = ri ? aw1 : aw0;
                float v[8];
#pragma unroll
                for (int h = 0; h < 8; h++) v[h] = acc[h][bn][ri * 2 + ci];
                float m = v[0];
#pragma unroll
                for (int h = 1; h < 8; h++) m = fmaxf(m, v[h]);
                float e[8], s = 0.f;
#pragma unroll
                for (int h = 0; h < 8; h++) { e[h] = __expf(v[h] - m); s += e[h]; }
                float w = __fdividef(aw, s);
#pragma unroll
                for (int h = 0; h < 8; h++) rk[ci][h] += w * e[h];
            }
#pragma unroll
        for (int ci = 0; ci < 2; ci++)
#pragma unroll
            for (int h = 0; h < 8; h++) {
                float r = rk[ci][h];
                r += __shfl_xor_sync(0xffffffffu, r, 4);
                r += __shfl_xor_sync(0xffffffffu, r, 8);
                r += __shfl_xor_sync(0xffffffffu, r, 16);
                if (l < 4) {
                    int kl = wk * 16 + bn * 8 + 2 * l + ci;
                    atomicAdd(&Rs[kl][h], r);
                }
            }
    }
    __syncthreads();
    atomicAdd(&g_R[(size_t)(ik + (t >> 3)) * H + (t & 7)], Rs[t >> 3][t & 7]);
}

// ---------------------------------------------------------------------------
// K4: T[b,h,m] = sum_k R[b,k,h] * X[b,k,m]
// ---------------------------------------------------------------------------
__global__ void __launch_bounds__(256) k4_T(const float* __restrict__ X) {
    __shared__ float Xs[64][64];
    __shared__ float Rsm[64][8];
    int b = blockIdx.y;
    int m0 = blockIdx.x * 64;
    int t = threadIdx.x;
    int m = t & 63, hh = t >> 6;
    float acc0 = 0.f, acc1 = 0.f;
    for (int kc = 0; kc < S; kc += 64) {
#pragma unroll
        for (int u = 0; u < 4; u++) {
            int lin = t + 256 * u;
            int r = lin >> 4, c = (lin & 15) << 2;
            *(float4*)&Xs[r][c] =
                *(const float4*)(X + (size_t)(b * S + kc + r) * DIM + m0 + c);
        }
        {
            float2 v = *(const float2*)(g_R + ((size_t)b * S + kc) * H + t * 2);
            *(float2*)&((float*)Rsm)[t * 2] = v;
        }
        __syncthreads();
#pragma unroll 8
        for (int k = 0; k < 64; k++) {
            float x = Xs[k][m];
            acc0 += Rsm[k][hh] * x;
            acc1 += Rsm[k][hh + 4] * x;
        }
        __syncthreads();
    }
    g_T[((size_t)b * H + hh) * DIM + m0 + m] = acc0;
    g_T[((size_t)b * H + hh + 4) * DIM + m0 + m] = acc1;
}

// ---------------------------------------------------------------------------
// K5: out[b,j] = sum_m Wv[j,m] * T[b, j&7, m]
// ---------------------------------------------------------------------------
__global__ void k5_out(const float* __restrict__ Wv, float* __restrict__ out) {
    int warp = threadIdx.x >> 5, lane = threadIdx.x & 31;
    int g = blockIdx.x * 8 + warp;
    int b = g / DIM, j = g % DIM;
    int h = j & 7;
    const float4* wr = (const float4*)(Wv + (size_t)j * DIM);
    const float4* tr = (const float4*)(g_T + ((size_t)b * H + h) * DIM);
    float s = 0.f;
#pragma unroll
    for (int i = 0; i < 6; i++) {
        float4 a = wr[lane + 32 * i];
        float4 c = tr[lane + 32 * i];
        s += a.x * c.x + a.y * c.y + a.z * c.z + a.w * c.w;
    }
#pragma unroll
    for (int o = 16; o; o >>= 1) s += __shfl_xor_sync(0xffffffffu, s, o);
    if (lane == 0) out[(size_t)b * DIM + j] = s;
}

// ---------------------------------------------------------------------------
extern "C" void kernel_launch(void* const* d_in, const int* in_sizes, int n_in,
                              void* d_out, int out_size) {
    const float* X    = (const float*)d_in[0];
    const int*   tags = (const int*)d_in[1];
    const float* w    = (const float*)d_in[2];
    const float* Wq   = (const float*)d_in[3];
    const float* Wk   = (const float*)d_in[4];
    const float* Wv   = (const float*)d_in[5];
    float* out = (float*)d_out;

    static int attr_set = 0;
    if (!attr_set) {
        cudaFuncSetAttribute(k3_attn, cudaFuncAttributeMaxDynamicSharedMemorySize,
                             8 * K3_TILE * (int)sizeof(__nv_bfloat16));  // 192 KB
        attr_set = 1;
    }

    k0_zeroR<<<(NI * H + 255) / 256, 256>>>();
    ksplit_sel<<<(NI * DIM / 4 + 255) / 256, 256>>>(X, 0, NI * DIM / 4);
    ksplit_sel<<<(DIM * DIM / 4 + 255) / 256, 256>>>(Wq, 1, DIM * DIM / 4);
    ksplit_sel<<<(DIM * DIM / 4 + 255) / 256, 256>>>(Wk, 2, DIM * DIM / 4);
    k1a_logits<<<NI / 8, 256>>>(X, tags, w);
    k1b_softmax<<<B, 256>>>();
    k2_mma<<<dim3(64, 12), 256, 2 * K2_BUF * sizeof(__nv_bfloat16)>>>();
    k3_attn<<<dim3(16, 16, 8), 512, 8 * K3_TILE * sizeof(__nv_bfloat16)>>>();
    k4_T<<<dim3(12, 8), 256>>>(X);
    k5_out<<<768, 256>>>(Wv, out);
}